// round 6
// baseline (speedup 1.0000x reference)
#include <cuda_runtime.h>
#include <cuda_bf16.h>
#include <math.h>
#include <stdint.h>

// ---------------- problem constants ----------------
#define BATCH   2
#define TSEQ    512
#define NTOK    1024
#define DMODEL  1024
#define NHEADS  8
#define DKEY    128
#define HK      1024
#define NSUB    128
#define TOPK    16
#define HD      128

// ---------------- scratch ----------------
__device__ __align__(128) float g_q[NTOK * HK];
__device__ __align__(128) float g_qkv[NTOK * 3 * DMODEL];
__device__ __align__(128) float g_att[BATCH * NHEADS * TSEQ * TSEQ];   // 16 MB
__device__ __align__(128) float g_sum[NTOK * DMODEL];

__device__ __align__(128) __nv_bfloat16 g_x_hi[NTOK * DMODEL],  g_x_lo[NTOK * DMODEL];
__device__ __align__(128) __nv_bfloat16 g_w1_hi[4096 * DMODEL], g_w1_lo[4096 * DMODEL]; // [wq;in_proj]
__device__ __align__(128) __nv_bfloat16 g_w2_hi[DMODEL * 2048], g_w2_lo[DMODEL * 2048]; // [wo|attn_ow]
__device__ __align__(128) __nv_bfloat16 g_cat_hi[NTOK * 2048],  g_cat_lo[NTOK * 2048];  // [peer|ao]

// ---------------- helpers ----------------
__device__ __forceinline__ uint32_t smem_u32(const void* p) {
    uint32_t a;
    asm("{ .reg .u64 t; cvta.to.shared.u64 t, %1; cvt.u32.u64 %0, t; }"
        : "=r"(a) : "l"(p));
    return a;
}
#define LDSM4(r, addr) \
    asm volatile("ldmatrix.sync.aligned.m8n8.x4.shared.b16 {%0,%1,%2,%3}, [%4];" \
        : "=r"((r)[0]), "=r"((r)[1]), "=r"((r)[2]), "=r"((r)[3]) : "r"(addr))
#define MMA_BF16(d, a, b0, b1) \
    asm volatile("mma.sync.aligned.m16n8k16.row.col.f32.bf16.bf16.f32 " \
        "{%0,%1,%2,%3}, {%4,%5,%6,%7}, {%8,%9}, {%0,%1,%2,%3};" \
        : "+f"((d)[0]), "+f"((d)[1]), "+f"((d)[2]), "+f"((d)[3]) \
        : "r"((a)[0]), "r"((a)[1]), "r"((a)[2]), "r"((a)[3]), "r"(b0), "r"(b1))
#define CP16(dst, src) \
    asm volatile("cp.async.cg.shared.global [%0], [%1], 16;" :: "r"(dst), "l"(src))
#define CP_COMMIT() asm volatile("cp.async.commit_group;" ::: "memory")
#define CP_WAIT1()  asm volatile("cp.async.wait_group 1;" ::: "memory")

// ============================================================================
// split kernels (fp32 -> bf16 hi/lo)
// ============================================================================
__device__ __forceinline__ void split_store4(float4 v, __nv_bfloat16* hi,
                                             __nv_bfloat16* lo, size_t i4) {
    float vv[4] = {v.x, v.y, v.z, v.w};
    __nv_bfloat16 h[4], l[4];
#pragma unroll
    for (int k = 0; k < 4; k++) {
        h[k] = __float2bfloat16(vv[k]);
        l[k] = __float2bfloat16(vv[k] - __bfloat162float(h[k]));
    }
    ((__nv_bfloat162*)hi)[2 * i4]     = __nv_bfloat162(h[0], h[1]);
    ((__nv_bfloat162*)hi)[2 * i4 + 1] = __nv_bfloat162(h[2], h[3]);
    ((__nv_bfloat162*)lo)[2 * i4]     = __nv_bfloat162(l[0], l[1]);
    ((__nv_bfloat162*)lo)[2 * i4 + 1] = __nv_bfloat162(l[2], l[3]);
}

__global__ void __launch_bounds__(256) split_x(const float* __restrict__ src) {
    size_t i = (size_t)blockIdx.x * 256 + threadIdx.x;
    split_store4(((const float4*)src)[i], g_x_hi, g_x_lo, i);
}
__global__ void __launch_bounds__(256) split_w1(const float* __restrict__ wq,
                                                const float* __restrict__ ipw) {
    size_t i = (size_t)blockIdx.x * 256 + threadIdx.x;
    const size_t cut = (size_t)1024 * 1024 / 4;
    float4 v = (i < cut) ? ((const float4*)wq)[i] : ((const float4*)ipw)[i - cut];
    split_store4(v, g_w1_hi, g_w1_lo, i);
}
__global__ void __launch_bounds__(256) split_w2(const float* __restrict__ wo,
                                                const float* __restrict__ aow) {
    size_t i = (size_t)blockIdx.x * 256 + threadIdx.x;
    int row = (int)(i >> 9);
    int c4  = (int)(i & 511);
    float4 v = (c4 < 256) ? ((const float4*)wo)[row * 256 + c4]
                          : ((const float4*)aow)[row * 256 + c4 - 256];
    split_store4(v, g_w2_hi, g_w2_lo, i);
}

// ============================================================================
// bf16-split "3M" GEMM: CTA 128x128, BK=32, 8 warps (2x4), warp tile 64x32.
// 3-stage cp.async pipeline, ONE __syncthreads per K-iteration.
// bias_mode 0: bias[col] = col<ncut ? biasA[col] : biasB[col-ncut]
// bias_mode 1: bias[col] = biasA[col] + biasB[col]
// ============================================================================
#define A_T   (128 * 80)          // 10240 B per hi (or lo) tile
#define STAGE (4 * A_T)           // 40960 B
#define GEMM_SMEM (3 * STAGE)     // 122880 B

__global__ void __launch_bounds__(256) gemm_mma4(
    const __nv_bfloat16* __restrict__ Ahi, const __nv_bfloat16* __restrict__ Alo,
    const __nv_bfloat16* __restrict__ Bhi, const __nv_bfloat16* __restrict__ Blo,
    const float* __restrict__ biasA, const float* __restrict__ biasB, int bias_mode,
    float* __restrict__ C0, int ld0, float* __restrict__ C1, int ld1, int ncut,
    int K)
{
    extern __shared__ char smc[];
    uint32_t base = smem_u32(smc);
    int t = threadIdx.x, warp = t >> 5, lane = t & 31;
    int m0 = blockIdx.y * 128, n0 = blockIdx.x * 128;
    int wm = warp >> 2, wn = warp & 3;

    float acc[4][4][4];
#pragma unroll
    for (int i = 0; i < 4; i++)
#pragma unroll
        for (int j = 0; j < 4; j++)
#pragma unroll
            for (int r = 0; r < 4; r++) acc[i][j][r] = 0.f;

    const int niter = K >> 5;

    auto issue = [&](int it) {
        uint32_t sb = base + (it % 3) * STAGE;
        int k0 = it << 5;
#pragma unroll
        for (int p = 0; p < 2; p++) {     // A: 128 rows x 4 x 16B chunks
            int c = t + p * 256;
            int row = c >> 2, j = c & 3;
            const __nv_bfloat16* sh = Ahi + (size_t)(m0 + row) * K + k0 + j * 8;
            const __nv_bfloat16* sl = Alo + (size_t)(m0 + row) * K + k0 + j * 8;
            uint32_t d = sb + (uint32_t)(row * 80 + j * 16);
            CP16(d, sh);
            CP16(d + A_T, sl);
        }
#pragma unroll
        for (int p = 0; p < 2; p++) {     // B: 128 rows x 4 x 16B chunks
            int c = t + p * 256;
            int row = c >> 2, j = c & 3;
            const __nv_bfloat16* sh = Bhi + (size_t)(n0 + row) * K + k0 + j * 8;
            const __nv_bfloat16* sl = Blo + (size_t)(n0 + row) * K + k0 + j * 8;
            uint32_t d = sb + 2 * A_T + (uint32_t)(row * 80 + j * 16);
            CP16(d, sh);
            CP16(d + A_T, sl);
        }
    };

    issue(0); CP_COMMIT();
    issue(1); CP_COMMIT();

    uint32_t a_off = (uint32_t)((wm * 64 + (lane & 15)) * 80 + (lane >> 4) * 16);
    uint32_t b_off = (uint32_t)((wn * 32 + (lane & 15)) * 80 + (lane >> 4) * 16);

    for (int it = 0; it < niter; ++it) {
        CP_WAIT1();
        __syncthreads();                   // sole barrier: all warps done with it-1
        if (it + 2 < niter) issue(it + 2); // writes stage (it-1)%3 — safe post-barrier
        CP_COMMIT();

        uint32_t sb = base + (it % 3) * STAGE;
        uint32_t sa_h = sb, sa_l = sb + A_T;
        uint32_t sb_h = sb + 2 * A_T, sb_l = sb + 3 * A_T;

#pragma unroll
        for (int ks = 0; ks < 2; ks++) {
            uint32_t kb = ks * 32;
            uint32_t ah[4][4], al[4][4], bh[2][4], bl[2][4];
#pragma unroll
            for (int mt = 0; mt < 4; mt++) {
                uint32_t o = a_off + mt * 16 * 80 + kb;
                LDSM4(ah[mt], sa_h + o);
                LDSM4(al[mt], sa_l + o);
            }
#pragma unroll
            for (int bt = 0; bt < 2; bt++) {
                uint32_t o = b_off + bt * 16 * 80 + kb;
                LDSM4(bh[bt], sb_h + o);
                LDSM4(bl[bt], sb_l + o);
            }
#pragma unroll
            for (int mt = 0; mt < 4; mt++) {
#pragma unroll
                for (int nt = 0; nt < 4; nt++) {
                    int bt = nt >> 1, s2 = nt & 1;
                    MMA_BF16(acc[mt][nt], ah[mt], bh[bt][s2], bh[bt][s2 + 2]);
                    MMA_BF16(acc[mt][nt], al[mt], bh[bt][s2], bh[bt][s2 + 2]);
                    MMA_BF16(acc[mt][nt], ah[mt], bl[bt][s2], bl[bt][s2 + 2]);
                }
            }
        }
    }

    // ---- epilogue ----
    int g = lane >> 2, c2 = lane & 3;
#pragma unroll
    for (int mt = 0; mt < 4; mt++) {
#pragma unroll
        for (int nt = 0; nt < 4; nt++) {
            int row = m0 + wm * 64 + mt * 16 + g;
            int col = n0 + wn * 32 + nt * 8 + 2 * c2;
            float b0, b1;
            if (bias_mode == 0) {
                b0 = (col < ncut) ? biasA[col] : biasB[col - ncut];
                b1 = (col + 1 < ncut) ? biasA[col + 1] : biasB[col + 1 - ncut];
            } else {
                b0 = biasA[col] + biasB[col];
                b1 = biasA[col + 1] + biasB[col + 1];
            }
            float* C; int ld, cc;
            if (col < ncut) { C = C0; ld = ld0; cc = col; }
            else            { C = C1; ld = ld1; cc = col - ncut; }
            *(float2*)(C + (size_t)row * ld + cc) =
                make_float2(acc[mt][nt][0] + b0, acc[mt][nt][1] + b1);
            *(float2*)(C + (size_t)(row + 8) * ld + cc) =
                make_float2(acc[mt][nt][2] + b0, acc[mt][nt][3] + b1);
        }
    }
}

// ============================================================================
// PEER routing -> writes bf16 hi/lo into cat cols [0,1024)
// ============================================================================
__global__ void __launch_bounds__(128) peer_route(
    const float* __restrict__ bn_w, const float* __restrict__ bn_b,
    const float* __restrict__ bn_mean, const float* __restrict__ bn_var,
    const float* __restrict__ sub_keys, const float* __restrict__ expert_w)
{
    int token = blockIdx.x >> 3;
    int head  = blockIdx.x & 7;
    int tid   = threadIdx.x;

    __shared__ float q[128];
    __shared__ float s1[128], s2[128];
    __shared__ float v1[16], v2[16];
    __shared__ int   i1[16], i2[16];
    __shared__ float cval[256];
    __shared__ int   cidx[256];
    __shared__ int   sel[16];
    __shared__ float simv[16];
    __shared__ float rw[16];
    __shared__ float ews[16][128];

    int c = head * 128 + tid;
    float qraw = g_q[(size_t)token * HK + c];
    float qb = (qraw - bn_mean[c]) * rsqrtf(bn_var[c] + 1e-5f) * bn_w[c] + bn_b[c];
    q[tid] = qb;
    __syncthreads();

    float a1 = 0.f, a2 = 0.f;
    const float* k1p = sub_keys + (size_t)tid * 64;
    const float* k2p = sub_keys + (size_t)NSUB * 64 + (size_t)tid * 64;
#pragma unroll 8
    for (int i = 0; i < 64; i++) {
        a1 += q[i]      * k1p[i];
        a2 += q[64 + i] * k2p[i];
    }
    s1[tid] = a1; s2[tid] = a2;
    __syncthreads();

    int r1 = 0, r2 = 0;
    for (int j = 0; j < 128; j++) {
        float x1 = s1[j]; r1 += (x1 > a1) || (x1 == a1 && j < tid);
        float x2 = s2[j]; r2 += (x2 > a2) || (x2 == a2 && j < tid);
    }
    if (r1 < 16) { v1[r1] = a1; i1[r1] = tid; }
    if (r2 < 16) { v2[r2] = a2; i2[r2] = tid; }
    __syncthreads();

    for (int p = tid; p < 256; p += 128) {
        int a = p >> 4, bb = p & 15;
        cval[p] = v1[a] + v2[bb];
        cidx[p] = i1[a] * NSUB + i2[bb];
    }
    __syncthreads();
    for (int p = tid; p < 256; p += 128) {
        float v = cval[p];
        int r = 0;
        for (int j = 0; j < 256; j++) {
            float w = cval[j];
            r += (w > v) || (w == v && j < p);
        }
        if (r < 16) sel[r] = cidx[p];
    }
    __syncthreads();

#pragma unroll
    for (int k = 0; k < 16; k++)
        ews[k][tid] = expert_w[(size_t)sel[k] * DKEY + tid];
    __syncthreads();

    int k8 = tid >> 3, l8 = tid & 7;
    float part = 0.f;
#pragma unroll
    for (int i = 0; i < 16; i++) {
        int d = l8 * 16 + i;
        part += q[d] * ews[k8][d];
    }
    part += __shfl_down_sync(0xffffffffu, part, 4);
    part += __shfl_down_sync(0xffffffffu, part, 2);
    part += __shfl_down_sync(0xffffffffu, part, 1);
    if (l8 == 0) simv[k8] = part;
    __syncthreads();

    if (tid == 0) {
        float m = -INFINITY;
#pragma unroll
        for (int k = 0; k < 16; k++) m = fmaxf(m, simv[k]);
        float e[16]; float s = 0.f;
#pragma unroll
        for (int k = 0; k < 16; k++) { e[k] = expf(simv[k] - m); s += e[k]; }
        float inv = 1.f / s;
#pragma unroll
        for (int k = 0; k < 16; k++) rw[k] = e[k] * inv;
    }
    __syncthreads();

    float o = 0.f;
#pragma unroll
    for (int k = 0; k < 16; k++) o += rw[k] * ews[k][tid];
    size_t idx = (size_t)token * 2048 + c;
    __nv_bfloat16 h = __float2bfloat16(o);
    g_cat_hi[idx] = h;
    g_cat_lo[idx] = __float2bfloat16(o - __bfloat162float(h));
}

// ============================================================================
// Attention scores + softmax
// ============================================================================
__global__ void __launch_bounds__(256) attn_scores()
{
    int z = blockIdx.y;
    int b = z >> 3, h = z & 7;
    int q0 = blockIdx.x * 16;
    int t = threadIdx.x;

    __shared__ float qs[16][128];
    __shared__ float Ks[32][132];

#pragma unroll
    for (int s = 0; s < 2; s++) {
        int v = t + s * 256;
        int r = v >> 5, c4 = (v & 31) * 4;
        float4 val = *(const float4*)&g_qkv[(size_t)(b * TSEQ + q0 + r) * (3 * DMODEL) + h * HD + c4];
        *(float4*)&qs[r][c4] = val;
    }
    __syncthreads();

    int j  = t & 15;
    int rr = t >> 4;
    float sreg[32];

    for (int kt = 0; kt < 16; kt++) {
#pragma unroll
        for (int s = 0; s < 4; s++) {
            int v = t + s * 256;
            int kr = v >> 5, c4 = (v & 31) * 4;
            float4 val = *(const float4*)&g_qkv[(size_t)(b * TSEQ + kt * 32 + kr) * (3 * DMODEL) + DMODEL + h * HD + c4];
            Ks[kr][c4 + 0] = val.x; Ks[kr][c4 + 1] = val.y;
            Ks[kr][c4 + 2] = val.z; Ks[kr][c4 + 3] = val.w;
        }
        __syncthreads();
        float acc1 = 0.f, acc2 = 0.f;
        const float4* qr  = (const float4*)&qs[rr][0];
        const float4* ka4 = (const float4*)&Ks[j][0];
        const float4* kb4 = (const float4*)&Ks[j + 16][0];
#pragma unroll
        for (int i = 0; i < 32; i++) {
            float4 qv = qr[i];
            float4 a  = ka4[i];
            float4 bb = kb4[i];
            acc1 += qv.x * a.x + qv.y * a.y + qv.z * a.z + qv.w * a.w;
            acc2 += qv.x * bb.x + qv.y * bb.y + qv.z * bb.z + qv.w * bb.w;
        }
        sreg[2 * kt]     = acc1;
        sreg[2 * kt + 1] = acc2;
        __syncthreads();
    }

    const float scale = 0.08838834764831845f;
#pragma unroll
    for (int i = 0; i < 32; i++) sreg[i] *= scale;

    float m = -INFINITY;
#pragma unroll
    for (int i = 0; i < 32; i++) m = fmaxf(m, sreg[i]);
#pragma unroll
    for (int off = 8; off; off >>= 1)
        m = fmaxf(m, __shfl_xor_sync(0xffffffffu, m, off));
    float sum = 0.f;
#pragma unroll
    for (int i = 0; i < 32; i++) { sreg[i] = expf(sreg[i] - m); sum += sreg[i]; }
#pragma unroll
    for (int off = 8; off; off >>= 1)
        sum += __shfl_xor_sync(0xffffffffu, sum, off);
    float inv = 1.f / sum;

    float* arow = g_att + ((size_t)z * TSEQ + q0 + rr) * TSEQ;
#pragma unroll
    for (int kt = 0; kt < 16; kt++) {
        arow[kt * 32 + j]      = sreg[2 * kt] * inv;
        arow[kt * 32 + 16 + j] = sreg[2 * kt + 1] * inv;
    }
}

// ============================================================================
// AV GEMM (SIMT) -> writes bf16 hi/lo into cat cols [1024,2048)
// ============================================================================
__global__ void __launch_bounds__(256) gemm_av()
{
    int z = blockIdx.z;
    int b = z >> 3, h = z & 7;
    const float* A  = g_att + (size_t)z * TSEQ * TSEQ;
    const float* Bb = g_qkv + (size_t)b * TSEQ * (3 * DMODEL) + 2 * DMODEL + h * HD;

    __shared__ float As[16][128];
    __shared__ float Bs[16][64];
    int t  = threadIdx.x;
    int m0 = blockIdx.y * 128;
    int n0 = blockIdx.x * 64;
    int tx = t & 15, ty = t >> 4;

    float acc[8][4];
#pragma unroll
    for (int i = 0; i < 8; i++)
#pragma unroll
        for (int j = 0; j < 4; j++) acc[i][j] = 0.f;

    for (int k0 = 0; k0 < TSEQ; k0 += 16) {
#pragma unroll
        for (int s = 0; s < 2; s++) {
            int v = t + s * 256;
            int row = v >> 2, c4 = (v & 3) * 4;
            float4 a = *(const float4*)(A + (size_t)(m0 + row) * TSEQ + k0 + c4);
            As[c4 + 0][row] = a.x; As[c4 + 1][row] = a.y;
            As[c4 + 2][row] = a.z; As[c4 + 3][row] = a.w;
        }
        {
            int kr = t >> 4, c4 = (t & 15) * 4;
            float4 bv = *(const float4*)(Bb + (size_t)(k0 + kr) * (3 * DMODEL) + n0 + c4);
            *(float4*)&Bs[kr][c4] = bv;
        }
        __syncthreads();
#pragma unroll
        for (int kk = 0; kk < 16; kk++) {
            float ar[8], br[4];
#pragma unroll
            for (int i = 0; i < 8; i++) ar[i] = As[kk][ty * 8 + i];
#pragma unroll
            for (int jj = 0; jj < 4; jj++) br[jj] = Bs[kk][tx * 4 + jj];
#pragma unroll
            for (int i = 0; i < 8; i++)
#pragma unroll
                for (int jj = 0; jj < 4; jj++) acc[i][jj] += ar[i] * br[jj];
        }
        __syncthreads();
    }
#pragma unroll
    for (int i = 0; i < 8; i++) {
        int m = m0 + ty * 8 + i;
        int token = b * TSEQ + m;
#pragma unroll
        for (int jj = 0; jj < 4; jj++) {
            float v = acc[i][jj];
            size_t idx = (size_t)token * 2048 + 1024 + h * HD + n0 + tx * 4 + jj;
            __nv_bfloat16 hh = __float2bfloat16(v);
            g_cat_hi[idx] = hh;
            g_cat_lo[idx] = __float2bfloat16(v - __bfloat162float(hh));
        }
    }
}

// mean over heads
__global__ void __launch_bounds__(256) attn_mean(float* __restrict__ out)
{
    int idx = blockIdx.x * 256 + threadIdx.x;
    int b   = idx / (TSEQ * TSEQ);
    int rem = idx - b * (TSEQ * TSEQ);
    float s = 0.f;
#pragma unroll
    for (int h = 0; h < 8; h++)
        s += g_att[((size_t)(b * 8 + h)) * (TSEQ * TSEQ) + rem];
    out[idx] = s * 0.125f;
}

// y = rmsnorm(x + g_sum) * rms_w
__global__ void __launch_bounds__(256) final_rms(
    const float* __restrict__ x, const float* __restrict__ rms_w,
    float* __restrict__ y)
{
    int token = blockIdx.x;
    int t = threadIdx.x;
    size_t base = (size_t)token * DMODEL;
    float v[4];
    float ss = 0.f;
#pragma unroll
    for (int u = 0; u < 4; u++) {
        int c = t + u * 256;
        float s = x[base + c] + g_sum[base + c];
        v[u] = s;
        ss += s * s;
    }
#pragma unroll
    for (int off = 16; off; off >>= 1)
        ss += __shfl_xor_sync(0xffffffffu, ss, off);
    __shared__ float red[8];
    __shared__ float stot;
    if ((t & 31) == 0) red[t >> 5] = ss;
    __syncthreads();
    if (t == 0) {
        float s = 0.f;
#pragma unroll
        for (int i = 0; i < 8; i++) s += red[i];
        stot = rsqrtf(s * (1.f / DMODEL) + 1e-6f);
    }
    __syncthreads();
    float inv = stot;
#pragma unroll
    for (int u = 0; u < 4; u++) {
        int c = t + u * 256;
        y[base + c] = v[u] * inv * rms_w[c];
    }
}

// ============================================================================
extern "C" void kernel_launch(void* const* d_in, const int* in_sizes, int n_in,
                              void* d_out, int out_size)
{
    const float* x         = (const float*)d_in[0];
    const float* wq        = (const float*)d_in[1];
    const float* bq        = (const float*)d_in[2];
    const float* bn_w      = (const float*)d_in[3];
    const float* bn_b      = (const float*)d_in[4];
    const float* bn_mean   = (const float*)d_in[5];
    const float* bn_var    = (const float*)d_in[6];
    const float* sub_keys  = (const float*)d_in[7];
    const float* expert_w  = (const float*)d_in[8];
    const float* wo        = (const float*)d_in[9];
    const float* bo        = (const float*)d_in[10];
    const float* in_proj_w = (const float*)d_in[11];
    const float* in_proj_b = (const float*)d_in[12];
    const float* attn_ow   = (const float*)d_in[13];
    const float* attn_ob   = (const float*)d_in[14];
    const float* rms_w     = (const float*)d_in[15];

    float* y      = (float*)d_out;
    float* attn_w = (float*)d_out + (size_t)NTOK * DMODEL;

    void *p_q, *p_qkv, *p_sum;
    cudaGetSymbolAddress(&p_q, g_q);
    cudaGetSymbolAddress(&p_qkv, g_qkv);
    cudaGetSymbolAddress(&p_sum, g_sum);

    void *xh, *xl, *w1h, *w1l, *w2h, *w2l, *ch, *cl;
    cudaGetSymbolAddress(&xh,  g_x_hi);  cudaGetSymbolAddress(&xl,  g_x_lo);
    cudaGetSymbolAddress(&w1h, g_w1_hi); cudaGetSymbolAddress(&w1l, g_w1_lo);
    cudaGetSymbolAddress(&w2h, g_w2_hi); cudaGetSymbolAddress(&w2l, g_w2_lo);
    cudaGetSymbolAddress(&ch,  g_cat_hi); cudaGetSymbolAddress(&cl, g_cat_lo);

    cudaFuncSetAttribute(gemm_mma4, cudaFuncAttributeMaxDynamicSharedMemorySize,
                         GEMM_SMEM);

    // [0..2] splits
    split_x <<<(NTOK * DMODEL) / 1024, 256>>>(x);
    split_w1<<<(4096 * DMODEL) / 1024, 256>>>(wq, in_proj_w);
    split_w2<<<(DMODEL * 2048) / 1024, 256>>>(wo, attn_ow);

    // [3] fused q+qkv GEMM  (ncu captures launch index 3)
    gemm_mma4<<<dim3(4096 / 128, NTOK / 128), 256, GEMM_SMEM>>>(
        (const __nv_bfloat16*)xh, (const __nv_bfloat16*)xl,
        (const __nv_bfloat16*)w1h, (const __nv_bfloat16*)w1l,
        bq, in_proj_b, 0,
        (float*)p_q, HK, (float*)p_qkv, 3 * DMODEL, 1024, DMODEL);

    // PEER routing
    peer_route<<<NTOK * NHEADS, 128>>>(bn_w, bn_b, bn_mean, bn_var, sub_keys, expert_w);

    // attention
    attn_scores<<<dim3(TSEQ / 16, BATCH * NHEADS), 256>>>();
    gemm_av<<<dim3(HD / 64, TSEQ / 128, BATCH * NHEADS), 256>>>();
    attn_mean<<<(BATCH * TSEQ * TSEQ) / 256, 256>>>(attn_w);

    // fused output projection: cat(1024x2048) @ w2(1024x2048)^T -> g_sum
    gemm_mma4<<<dim3(DMODEL / 128, NTOK / 128), 256, GEMM_SMEM>>>(
        (const __nv_bfloat16*)ch, (const __nv_bfloat16*)cl,
        (const __nv_bfloat16*)w2h, (const __nv_bfloat16*)w2l,
        bo, attn_ob, 1,
        (float*)p_sum, DMODEL, (float*)p_sum, DMODEL, 1 << 30, 2048);

    // residual + rmsnorm
    final_rms<<<NTOK, 256>>>(x, rms_w, y);

    (void)in_sizes; (void)n_in; (void)out_size;
}

// round 7
// speedup vs baseline: 1.0662x; 1.0662x over previous
#include <cuda_runtime.h>
#include <cuda_bf16.h>
#include <math.h>
#include <stdint.h>

// ---------------- problem constants ----------------
#define BATCH   2
#define TSEQ    512
#define NTOK    1024
#define DMODEL  1024
#define NHEADS  8
#define DKEY    128
#define HK      1024
#define NSUB    128
#define TOPK    16
#define HD      128

// ---------------- scratch ----------------
__device__ __align__(128) float g_q[NTOK * HK];
__device__ __align__(128) float g_qkv[NTOK * 3 * DMODEL];
__device__ __align__(128) float g_att[BATCH * NHEADS * TSEQ * TSEQ];   // 16 MB
__device__ __align__(128) float g_sum[NTOK * DMODEL];

__device__ __align__(128) __nv_bfloat16 g_x_hi[NTOK * DMODEL],  g_x_lo[NTOK * DMODEL];
__device__ __align__(128) __nv_bfloat16 g_w1_hi[4096 * DMODEL], g_w1_lo[4096 * DMODEL]; // [wq;in_proj]
__device__ __align__(128) __nv_bfloat16 g_w2_hi[DMODEL * 2048], g_w2_lo[DMODEL * 2048]; // [wo|attn_ow]
__device__ __align__(128) __nv_bfloat16 g_cat_hi[NTOK * 2048],  g_cat_lo[NTOK * 2048];  // [peer|ao]

// ---------------- helpers ----------------
__device__ __forceinline__ uint32_t smem_u32(const void* p) {
    uint32_t a;
    asm("{ .reg .u64 t; cvta.to.shared.u64 t, %1; cvt.u32.u64 %0, t; }"
        : "=r"(a) : "l"(p));
    return a;
}
#define LDSM4(r, addr) \
    asm volatile("ldmatrix.sync.aligned.m8n8.x4.shared.b16 {%0,%1,%2,%3}, [%4];" \
        : "=r"((r)[0]), "=r"((r)[1]), "=r"((r)[2]), "=r"((r)[3]) : "r"(addr))
#define MMA_BF16(d, a, b0, b1) \
    asm volatile("mma.sync.aligned.m16n8k16.row.col.f32.bf16.bf16.f32 " \
        "{%0,%1,%2,%3}, {%4,%5,%6,%7}, {%8,%9}, {%0,%1,%2,%3};" \
        : "+f"((d)[0]), "+f"((d)[1]), "+f"((d)[2]), "+f"((d)[3]) \
        : "r"((a)[0]), "r"((a)[1]), "r"((a)[2]), "r"((a)[3]), "r"(b0), "r"(b1))
#define CP16(dst, src) \
    asm volatile("cp.async.cg.shared.global [%0], [%1], 16;" :: "r"(dst), "l"(src))
#define CP_COMMIT() asm volatile("cp.async.commit_group;" ::: "memory")
#define CP_WAIT0()  asm volatile("cp.async.wait_group 0;" ::: "memory")

// ============================================================================
// combined split kernel: fp32 -> bf16 hi/lo for x, w1=[wq;in_proj], w2=[wo|attn_ow]
// grid covers 1M + 4M + 2M = 7M elements / 4 per thread
// ============================================================================
__device__ __forceinline__ void split_store4(float4 v, __nv_bfloat16* hi,
                                             __nv_bfloat16* lo, size_t i4) {
    float vv[4] = {v.x, v.y, v.z, v.w};
    __nv_bfloat16 h[4], l[4];
#pragma unroll
    for (int k = 0; k < 4; k++) {
        h[k] = __float2bfloat16(vv[k]);
        l[k] = __float2bfloat16(vv[k] - __bfloat162float(h[k]));
    }
    ((__nv_bfloat162*)hi)[2 * i4]     = __nv_bfloat162(h[0], h[1]);
    ((__nv_bfloat162*)hi)[2 * i4 + 1] = __nv_bfloat162(h[2], h[3]);
    ((__nv_bfloat162*)lo)[2 * i4]     = __nv_bfloat162(l[0], l[1]);
    ((__nv_bfloat162*)lo)[2 * i4 + 1] = __nv_bfloat162(l[2], l[3]);
}

#define X4   ((size_t)NTOK * DMODEL / 4)        // 262144
#define W14  ((size_t)4096 * DMODEL / 4)        // 1048576
#define W24  ((size_t)DMODEL * 2048 / 4)        // 524288

__global__ void __launch_bounds__(256) split_all(
    const float* __restrict__ x,  const float* __restrict__ wq,
    const float* __restrict__ ipw, const float* __restrict__ wo,
    const float* __restrict__ aow)
{
    size_t i = (size_t)blockIdx.x * 256 + threadIdx.x;
    if (i < X4) {
        split_store4(((const float4*)x)[i], g_x_hi, g_x_lo, i);
    } else if (i < X4 + W14) {
        size_t j = i - X4;
        const size_t cut = (size_t)1024 * 1024 / 4;
        float4 v = (j < cut) ? ((const float4*)wq)[j] : ((const float4*)ipw)[j - cut];
        split_store4(v, g_w1_hi, g_w1_lo, j);
    } else {
        size_t j = i - X4 - W14;
        int row = (int)(j >> 9);
        int c4  = (int)(j & 511);
        float4 v = (c4 < 256) ? ((const float4*)wo)[row * 256 + c4]
                              : ((const float4*)aow)[row * 256 + c4 - 256];
        split_store4(v, g_w2_hi, g_w2_lo, j);
    }
}

// ============================================================================
// bf16-split "3M" GEMM. Template MT: CTA tile = (32*MT) x 128, warp tile (16*MT)x32.
// BK=32, 8 warps (2 x 4). 2-stage cp.async pipeline -> 2 CTAs/SM.
// bias_mode 0: bias[col] = col<ncut ? biasA[col] : biasB[col-ncut]
// bias_mode 1: bias[col] = biasA[col] + biasB[col]
// ============================================================================
template<int MT>
__global__ void __launch_bounds__(256, 2) gemm_mma(
    const __nv_bfloat16* __restrict__ Ahi, const __nv_bfloat16* __restrict__ Alo,
    const __nv_bfloat16* __restrict__ Bhi, const __nv_bfloat16* __restrict__ Blo,
    const float* __restrict__ biasA, const float* __restrict__ biasB, int bias_mode,
    float* __restrict__ C0, int ld0, float* __restrict__ C1, int ld1, int ncut,
    int K)
{
    constexpr int CM   = 32 * MT;            // CTA rows
    constexpr int A_T  = CM * 80;            // bytes per A hi (or lo) tile
    constexpr int B_T  = 128 * 80;
    constexpr int STG  = 2 * A_T + 2 * B_T;  // one stage

    extern __shared__ char smc[];
    uint32_t base = smem_u32(smc);
    int t = threadIdx.x, warp = t >> 5, lane = t & 31;
    int m0 = blockIdx.y * CM, n0 = blockIdx.x * 128;
    int wm = warp >> 2, wn = warp & 3;

    float acc[MT][4][4];
#pragma unroll
    for (int i = 0; i < MT; i++)
#pragma unroll
        for (int j = 0; j < 4; j++)
#pragma unroll
            for (int r = 0; r < 4; r++) acc[i][j][r] = 0.f;

    const int niter = K >> 5;

    auto issue = [&](int it) {
        uint32_t sb = base + (it & 1) * STG;
        int k0 = it << 5;
#pragma unroll
        for (int p = 0; p < CM / 64; p++) {  // A: CM rows x 4 x 16B chunks
            int c = t + p * 256;
            int row = c >> 2, j = c & 3;
            const __nv_bfloat16* sh = Ahi + (size_t)(m0 + row) * K + k0 + j * 8;
            const __nv_bfloat16* sl = Alo + (size_t)(m0 + row) * K + k0 + j * 8;
            uint32_t d = sb + (uint32_t)(row * 80 + j * 16);
            CP16(d, sh);
            CP16(d + A_T, sl);
        }
#pragma unroll
        for (int p = 0; p < 2; p++) {        // B: 128 rows x 4 x 16B chunks
            int c = t + p * 256;
            int row = c >> 2, j = c & 3;
            const __nv_bfloat16* sh = Bhi + (size_t)(n0 + row) * K + k0 + j * 8;
            const __nv_bfloat16* sl = Blo + (size_t)(n0 + row) * K + k0 + j * 8;
            uint32_t d = sb + 2 * A_T + (uint32_t)(row * 80 + j * 16);
            CP16(d, sh);
            CP16(d + B_T, sl);
        }
    };

    issue(0); CP_COMMIT();

    uint32_t a_off = (uint32_t)((wm * (16 * MT) + (lane & 15)) * 80 + (lane >> 4) * 16);
    uint32_t b_off = (uint32_t)((wn * 32 + (lane & 15)) * 80 + (lane >> 4) * 16);

    for (int it = 0; it < niter; ++it) {
        CP_WAIT0();          // stage it&1 landed (sole outstanding group)
        __syncthreads();     // visible to all; all warps done computing it-1
        if (it + 1 < niter) { issue(it + 1); CP_COMMIT(); }  // overlaps compute below

        uint32_t sb = base + (it & 1) * STG;
        uint32_t sa_h = sb, sa_l = sb + A_T;
        uint32_t sb_h = sb + 2 * A_T, sb_l = sb + 2 * A_T + B_T;

#pragma unroll
        for (int ks = 0; ks < 2; ks++) {
            uint32_t kb = ks * 32;
            uint32_t ah[MT][4], al[MT][4], bh[2][4], bl[2][4];
#pragma unroll
            for (int mt = 0; mt < MT; mt++) {
                uint32_t o = a_off + mt * 16 * 80 + kb;
                LDSM4(ah[mt], sa_h + o);
                LDSM4(al[mt], sa_l + o);
            }
#pragma unroll
            for (int bt = 0; bt < 2; bt++) {
                uint32_t o = b_off + bt * 16 * 80 + kb;
                LDSM4(bh[bt], sb_h + o);
                LDSM4(bl[bt], sb_l + o);
            }
            // term-major: dependent updates to same acc are MT*4 apart
#pragma unroll
            for (int mt = 0; mt < MT; mt++)
#pragma unroll
                for (int nt = 0; nt < 4; nt++)
                    MMA_BF16(acc[mt][nt], ah[mt], bh[nt >> 1][nt & 1], bh[nt >> 1][(nt & 1) + 2]);
#pragma unroll
            for (int mt = 0; mt < MT; mt++)
#pragma unroll
                for (int nt = 0; nt < 4; nt++)
                    MMA_BF16(acc[mt][nt], al[mt], bh[nt >> 1][nt & 1], bh[nt >> 1][(nt & 1) + 2]);
#pragma unroll
            for (int mt = 0; mt < MT; mt++)
#pragma unroll
                for (int nt = 0; nt < 4; nt++)
                    MMA_BF16(acc[mt][nt], ah[mt], bl[nt >> 1][nt & 1], bl[nt >> 1][(nt & 1) + 2]);
        }
    }

    // ---- epilogue ----
    int g = lane >> 2, c2 = lane & 3;
#pragma unroll
    for (int mt = 0; mt < MT; mt++) {
#pragma unroll
        for (int nt = 0; nt < 4; nt++) {
            int row = m0 + wm * (16 * MT) + mt * 16 + g;
            int col = n0 + wn * 32 + nt * 8 + 2 * c2;
            float b0, b1;
            if (bias_mode == 0) {
                b0 = (col < ncut) ? biasA[col] : biasB[col - ncut];
                b1 = (col + 1 < ncut) ? biasA[col + 1] : biasB[col + 1 - ncut];
            } else {
                b0 = biasA[col] + biasB[col];
                b1 = biasA[col + 1] + biasB[col + 1];
            }
            float* C; int ld, cc;
            if (col < ncut) { C = C0; ld = ld0; cc = col; }
            else            { C = C1; ld = ld1; cc = col - ncut; }
            *(float2*)(C + (size_t)row * ld + cc) =
                make_float2(acc[mt][nt][0] + b0, acc[mt][nt][1] + b1);
            *(float2*)(C + (size_t)(row + 8) * ld + cc) =
                make_float2(acc[mt][nt][2] + b0, acc[mt][nt][3] + b1);
        }
    }
}

// ============================================================================
// PEER routing -> writes bf16 hi/lo into cat cols [0,1024)
// ============================================================================
__global__ void __launch_bounds__(128) peer_route(
    const float* __restrict__ bn_w, const float* __restrict__ bn_b,
    const float* __restrict__ bn_mean, const float* __restrict__ bn_var,
    const float* __restrict__ sub_keys, const float* __restrict__ expert_w)
{
    int token = blockIdx.x >> 3;
    int head  = blockIdx.x & 7;
    int tid   = threadIdx.x;

    __shared__ float q[128];
    __shared__ float s1[128], s2[128];
    __shared__ float v1[16], v2[16];
    __shared__ int   i1[16], i2[16];
    __shared__ float cval[256];
    __shared__ int   cidx[256];
    __shared__ int   sel[16];
    __shared__ float simv[16];
    __shared__ float rw[16];
    __shared__ float ews[16][128];

    int c = head * 128 + tid;
    float qraw = g_q[(size_t)token * HK + c];
    float qb = (qraw - bn_mean[c]) * rsqrtf(bn_var[c] + 1e-5f) * bn_w[c] + bn_b[c];
    q[tid] = qb;
    __syncthreads();

    float a1 = 0.f, a2 = 0.f;
    const float* k1p = sub_keys + (size_t)tid * 64;
    const float* k2p = sub_keys + (size_t)NSUB * 64 + (size_t)tid * 64;
#pragma unroll 8
    for (int i = 0; i < 64; i++) {
        a1 += q[i]      * k1p[i];
        a2 += q[64 + i] * k2p[i];
    }
    s1[tid] = a1; s2[tid] = a2;
    __syncthreads();

    int r1 = 0, r2 = 0;
    for (int j = 0; j < 128; j++) {
        float x1 = s1[j]; r1 += (x1 > a1) || (x1 == a1 && j < tid);
        float x2 = s2[j]; r2 += (x2 > a2) || (x2 == a2 && j < tid);
    }
    if (r1 < 16) { v1[r1] = a1; i1[r1] = tid; }
    if (r2 < 16) { v2[r2] = a2; i2[r2] = tid; }
    __syncthreads();

    for (int p = tid; p < 256; p += 128) {
        int a = p >> 4, bb = p & 15;
        cval[p] = v1[a] + v2[bb];
        cidx[p] = i1[a] * NSUB + i2[bb];
    }
    __syncthreads();
    for (int p = tid; p < 256; p += 128) {
        float v = cval[p];
        int r = 0;
        for (int j = 0; j < 256; j++) {
            float w = cval[j];
            r += (w > v) || (w == v && j < p);
        }
        if (r < 16) sel[r] = cidx[p];
    }
    __syncthreads();

#pragma unroll
    for (int k = 0; k < 16; k++)
        ews[k][tid] = expert_w[(size_t)sel[k] * DKEY + tid];
    __syncthreads();

    int k8 = tid >> 3, l8 = tid & 7;
    float part = 0.f;
#pragma unroll
    for (int i = 0; i < 16; i++) {
        int d = l8 * 16 + i;
        part += q[d] * ews[k8][d];
    }
    part += __shfl_down_sync(0xffffffffu, part, 4);
    part += __shfl_down_sync(0xffffffffu, part, 2);
    part += __shfl_down_sync(0xffffffffu, part, 1);
    if (l8 == 0) simv[k8] = part;
    __syncthreads();

    if (tid == 0) {
        float m = -INFINITY;
#pragma unroll
        for (int k = 0; k < 16; k++) m = fmaxf(m, simv[k]);
        float e[16]; float s = 0.f;
#pragma unroll
        for (int k = 0; k < 16; k++) { e[k] = expf(simv[k] - m); s += e[k]; }
        float inv = 1.f / s;
#pragma unroll
        for (int k = 0; k < 16; k++) rw[k] = e[k] * inv;
    }
    __syncthreads();

    float o = 0.f;
#pragma unroll
    for (int k = 0; k < 16; k++) o += rw[k] * ews[k][tid];
    size_t idx = (size_t)token * 2048 + c;
    __nv_bfloat16 h = __float2bfloat16(o);
    g_cat_hi[idx] = h;
    g_cat_lo[idx] = __float2bfloat16(o - __bfloat162float(h));
}

// ============================================================================
// Attention scores + softmax
// ============================================================================
__global__ void __launch_bounds__(256) attn_scores()
{
    int z = blockIdx.y;
    int b = z >> 3, h = z & 7;
    int q0 = blockIdx.x * 16;
    int t = threadIdx.x;

    __shared__ float qs[16][128];
    __shared__ float Ks[32][132];

#pragma unroll
    for (int s = 0; s < 2; s++) {
        int v = t + s * 256;
        int r = v >> 5, c4 = (v & 31) * 4;
        float4 val = *(const float4*)&g_qkv[(size_t)(b * TSEQ + q0 + r) * (3 * DMODEL) + h * HD + c4];
        *(float4*)&qs[r][c4] = val;
    }
    __syncthreads();

    int j  = t & 15;
    int rr = t >> 4;
    float sreg[32];

    for (int kt = 0; kt < 16; kt++) {
#pragma unroll
        for (int s = 0; s < 4; s++) {
            int v = t + s * 256;
            int kr = v >> 5, c4 = (v & 31) * 4;
            float4 val = *(const float4*)&g_qkv[(size_t)(b * TSEQ + kt * 32 + kr) * (3 * DMODEL) + DMODEL + h * HD + c4];
            Ks[kr][c4 + 0] = val.x; Ks[kr][c4 + 1] = val.y;
            Ks[kr][c4 + 2] = val.z; Ks[kr][c4 + 3] = val.w;
        }
        __syncthreads();
        float acc1 = 0.f, acc2 = 0.f;
        const float4* qr  = (const float4*)&qs[rr][0];
        const float4* ka4 = (const float4*)&Ks[j][0];
        const float4* kb4 = (const float4*)&Ks[j + 16][0];
#pragma unroll
        for (int i = 0; i < 32; i++) {
            float4 qv = qr[i];
            float4 a  = ka4[i];
            float4 bb = kb4[i];
            acc1 += qv.x * a.x + qv.y * a.y + qv.z * a.z + qv.w * a.w;
            acc2 += qv.x * bb.x + qv.y * bb.y + qv.z * bb.z + qv.w * bb.w;
        }
        sreg[2 * kt]     = acc1;
        sreg[2 * kt + 1] = acc2;
        __syncthreads();
    }

    const float scale = 0.08838834764831845f;
#pragma unroll
    for (int i = 0; i < 32; i++) sreg[i] *= scale;

    float m = -INFINITY;
#pragma unroll
    for (int i = 0; i < 32; i++) m = fmaxf(m, sreg[i]);
#pragma unroll
    for (int off = 8; off; off >>= 1)
        m = fmaxf(m, __shfl_xor_sync(0xffffffffu, m, off));
    float sum = 0.f;
#pragma unroll
    for (int i = 0; i < 32; i++) { sreg[i] = expf(sreg[i] - m); sum += sreg[i]; }
#pragma unroll
    for (int off = 8; off; off >>= 1)
        sum += __shfl_xor_sync(0xffffffffu, sum, off);
    float inv = 1.f / sum;

    float* arow = g_att + ((size_t)z * TSEQ + q0 + rr) * TSEQ;
#pragma unroll
    for (int kt = 0; kt < 16; kt++) {
        arow[kt * 32 + j]      = sreg[2 * kt] * inv;
        arow[kt * 32 + 16 + j] = sreg[2 * kt + 1] * inv;
    }
}

// ============================================================================
// AV GEMM (SIMT) -> writes bf16 hi/lo into cat cols [1024,2048)
// ============================================================================
__global__ void __launch_bounds__(256) gemm_av()
{
    int z = blockIdx.z;
    int b = z >> 3, h = z & 7;
    const float* A  = g_att + (size_t)z * TSEQ * TSEQ;
    const float* Bb = g_qkv + (size_t)b * TSEQ * (3 * DMODEL) + 2 * DMODEL + h * HD;

    __shared__ float As[16][128];
    __shared__ float Bs[16][64];
    int t  = threadIdx.x;
    int m0 = blockIdx.y * 128;
    int n0 = blockIdx.x * 64;
    int tx = t & 15, ty = t >> 4;

    float acc[8][4];
#pragma unroll
    for (int i = 0; i < 8; i++)
#pragma unroll
        for (int j = 0; j < 4; j++) acc[i][j] = 0.f;

    for (int k0 = 0; k0 < TSEQ; k0 += 16) {
#pragma unroll
        for (int s = 0; s < 2; s++) {
            int v = t + s * 256;
            int row = v >> 2, c4 = (v & 3) * 4;
            float4 a = *(const float4*)(A + (size_t)(m0 + row) * TSEQ + k0 + c4);
            As[c4 + 0][row] = a.x; As[c4 + 1][row] = a.y;
            As[c4 + 2][row] = a.z; As[c4 + 3][row] = a.w;
        }
        {
            int kr = t >> 4, c4 = (t & 15) * 4;
            float4 bv = *(const float4*)(Bb + (size_t)(k0 + kr) * (3 * DMODEL) + n0 + c4);
            *(float4*)&Bs[kr][c4] = bv;
        }
        __syncthreads();
#pragma unroll
        for (int kk = 0; kk < 16; kk++) {
            float ar[8], br[4];
#pragma unroll
            for (int i = 0; i < 8; i++) ar[i] = As[kk][ty * 8 + i];
#pragma unroll
            for (int jj = 0; jj < 4; jj++) br[jj] = Bs[kk][tx * 4 + jj];
#pragma unroll
            for (int i = 0; i < 8; i++)
#pragma unroll
                for (int jj = 0; jj < 4; jj++) acc[i][jj] += ar[i] * br[jj];
        }
        __syncthreads();
    }
#pragma unroll
    for (int i = 0; i < 8; i++) {
        int m = m0 + ty * 8 + i;
        int token = b * TSEQ + m;
#pragma unroll
        for (int jj = 0; jj < 4; jj++) {
            float v = acc[i][jj];
            size_t idx = (size_t)token * 2048 + 1024 + h * HD + n0 + tx * 4 + jj;
            __nv_bfloat16 hh = __float2bfloat16(v);
            g_cat_hi[idx] = hh;
            g_cat_lo[idx] = __float2bfloat16(v - __bfloat162float(hh));
        }
    }
}

// mean over heads
__global__ void __launch_bounds__(256) attn_mean(float* __restrict__ out)
{
    int idx = blockIdx.x * 256 + threadIdx.x;
    int b   = idx / (TSEQ * TSEQ);
    int rem = idx - b * (TSEQ * TSEQ);
    float s = 0.f;
#pragma unroll
    for (int h = 0; h < 8; h++)
        s += g_att[((size_t)(b * 8 + h)) * (TSEQ * TSEQ) + rem];
    out[idx] = s * 0.125f;
}

// y = rmsnorm(x + g_sum) * rms_w
__global__ void __launch_bounds__(256) final_rms(
    const float* __restrict__ x, const float* __restrict__ rms_w,
    float* __restrict__ y)
{
    int token = blockIdx.x;
    int t = threadIdx.x;
    size_t base = (size_t)token * DMODEL;
    float v[4];
    float ss = 0.f;
#pragma unroll
    for (int u = 0; u < 4; u++) {
        int c = t + u * 256;
        float s = x[base + c] + g_sum[base + c];
        v[u] = s;
        ss += s * s;
    }
#pragma unroll
    for (int off = 16; off; off >>= 1)
        ss += __shfl_xor_sync(0xffffffffu, ss, off);
    __shared__ float red[8];
    __shared__ float stot;
    if ((t & 31) == 0) red[t >> 5] = ss;
    __syncthreads();
    if (t == 0) {
        float s = 0.f;
#pragma unroll
        for (int i = 0; i < 8; i++) s += red[i];
        stot = rsqrtf(s * (1.f / DMODEL) + 1e-6f);
    }
    __syncthreads();
    float inv = stot;
#pragma unroll
    for (int u = 0; u < 4; u++) {
        int c = t + u * 256;
        y[base + c] = v[u] * inv * rms_w[c];
    }
}

// ============================================================================
extern "C" void kernel_launch(void* const* d_in, const int* in_sizes, int n_in,
                              void* d_out, int out_size)
{
    const float* x         = (const float*)d_in[0];
    const float* wq        = (const float*)d_in[1];
    const float* bq        = (const float*)d_in[2];
    const float* bn_w      = (const float*)d_in[3];
    const float* bn_b      = (const float*)d_in[4];
    const float* bn_mean   = (const float*)d_in[5];
    const float* bn_var    = (const float*)d_in[6];
    const float* sub_keys  = (const float*)d_in[7];
    const float* expert_w  = (const float*)d_in[8];
    const float* wo        = (const float*)d_in[9];
    const float* bo        = (const float*)d_in[10];
    const float* in_proj_w = (const float*)d_in[11];
    const float* in_proj_b = (const float*)d_in[12];
    const float* attn_ow   = (const float*)d_in[13];
    const float* attn_ob   = (const float*)d_in[14];
    const float* rms_w     = (const float*)d_in[15];

    float* y      = (float*)d_out;
    float* attn_w = (float*)d_out + (size_t)NTOK * DMODEL;

    void *p_q, *p_qkv, *p_sum;
    cudaGetSymbolAddress(&p_q, g_q);
    cudaGetSymbolAddress(&p_qkv, g_qkv);
    cudaGetSymbolAddress(&p_sum, g_sum);

    void *xh, *xl, *w1h, *w1l, *w2h, *w2l, *ch, *cl;
    cudaGetSymbolAddress(&xh,  g_x_hi);  cudaGetSymbolAddress(&xl,  g_x_lo);
    cudaGetSymbolAddress(&w1h, g_w1_hi); cudaGetSymbolAddress(&w1l, g_w1_lo);
    cudaGetSymbolAddress(&w2h, g_w2_hi); cudaGetSymbolAddress(&w2l, g_w2_lo);
    cudaGetSymbolAddress(&ch,  g_cat_hi); cudaGetSymbolAddress(&cl, g_cat_lo);

    constexpr int SMEM4 = 2 * (2 * 128 * 80 + 2 * 128 * 80);  // 81920
    constexpr int SMEM2 = 2 * (2 * 64 * 80 + 2 * 128 * 80);   // 61440
    cudaFuncSetAttribute(gemm_mma<4>, cudaFuncAttributeMaxDynamicSharedMemorySize, SMEM4);
    cudaFuncSetAttribute(gemm_mma<2>, cudaFuncAttributeMaxDynamicSharedMemorySize, SMEM2);

    // [0] combined split
    split_all<<<(int)((X4 + W14 + W24) / 256), 256>>>(x, wq, in_proj_w, wo, attn_ow);

    // [1] fused q+qkv GEMM: x(1024x1024) @ w1(4096x1024)^T -> q | qkv
    gemm_mma<4><<<dim3(4096 / 128, NTOK / 128), 256, SMEM4>>>(
        (const __nv_bfloat16*)xh, (const __nv_bfloat16*)xl,
        (const __nv_bfloat16*)w1h, (const __nv_bfloat16*)w1l,
        bq, in_proj_b, 0,
        (float*)p_q, HK, (float*)p_qkv, 3 * DMODEL, 1024, DMODEL);

    // [2] attention scores (needs g_qkv only)
    attn_scores<<<dim3(TSEQ / 16, BATCH * NHEADS), 256>>>();

    // [3] PEER routing  <- ncu capture slot
    peer_route<<<NTOK * NHEADS, 128>>>(bn_w, bn_b, bn_mean, bn_var, sub_keys, expert_w);

    // [4..5] attention AV + mean
    gemm_av<<<dim3(HD / 64, TSEQ / 128, BATCH * NHEADS), 256>>>();
    attn_mean<<<(BATCH * TSEQ * TSEQ) / 256, 256>>>(attn_w);

    // [6] fused output projection: cat(1024x2048) @ w2(1024x2048)^T -> g_sum
    gemm_mma<2><<<dim3(DMODEL / 128, NTOK / 64), 256, SMEM2>>>(
        (const __nv_bfloat16*)ch, (const __nv_bfloat16*)cl,
        (const __nv_bfloat16*)w2h, (const __nv_bfloat16*)w2l,
        bo, attn_ob, 1,
        (float*)p_sum, DMODEL, (float*)p_sum, DMODEL, 1 << 30, 2048);

    // [7] residual + rmsnorm
    final_rms<<<NTOK, 256>>>(x, rms_w, y);

    (void)in_sizes; (void)n_in; (void)out_size;
}

// round 8
// speedup vs baseline: 2.2971x; 2.1545x over previous
#include <cuda_runtime.h>
#include <cuda_bf16.h>
#include <math.h>
#include <stdint.h>

// ---------------- problem constants ----------------
#define BATCH   2
#define TSEQ    512
#define NTOK    1024
#define DMODEL  1024
#define NHEADS  8
#define DKEY    128
#define HK      1024
#define NSUB    128
#define TOPK    16
#define HD      128

// ---------------- scratch ----------------
__device__ __align__(128) float g_q[NTOK * HK];          // BN'd q (fp32)
__device__ __align__(128) float g_qkv[NTOK * 3 * DMODEL];
__device__ __align__(128) float g_att[BATCH * NHEADS * TSEQ * TSEQ];   // 16 MB
__device__ __align__(128) float g_sum[NTOK * DMODEL];
__device__ __align__(128) float g_s[NTOK * NHEADS * 256];              // sub-key scores

__device__ __align__(128) __nv_bfloat16 g_x_hi[NTOK * DMODEL],  g_x_lo[NTOK * DMODEL];
__device__ __align__(128) __nv_bfloat16 g_w1_hi[4096 * DMODEL], g_w1_lo[4096 * DMODEL]; // [wq;in_proj]
__device__ __align__(128) __nv_bfloat16 g_w2_hi[DMODEL * 2048], g_w2_lo[DMODEL * 2048]; // [wo|attn_ow]
__device__ __align__(128) __nv_bfloat16 g_cat_hi[NTOK * 2048],  g_cat_lo[NTOK * 2048];  // [peer|ao]
__device__ __align__(128) __nv_bfloat16 g_qbn_hi[NTOK * HK],    g_qbn_lo[NTOK * HK];    // BN'd q bf16
__device__ __align__(128) __nv_bfloat16 g_bd_hi[256 * 128],     g_bd_lo[256 * 128];     // blockdiag subkeys

// 50 candidates (a,b) with (a+1)(b+1) <= 16 over rank-sorted v1,v2
__device__ const int CAND_A[50] = {0,0,0,0,0,0,0,0,0,0,0,0,0,0,0,0,
                                   1,1,1,1,1,1,1,1, 2,2,2,2,2, 3,3,3,3,
                                   4,4,4, 5,5, 6,6, 7,7, 8,9,10,11,12,13,14,15};
__device__ const int CAND_B[50] = {0,1,2,3,4,5,6,7,8,9,10,11,12,13,14,15,
                                   0,1,2,3,4,5,6,7, 0,1,2,3,4, 0,1,2,3,
                                   0,1,2, 0,1, 0,1, 0,1, 0,0,0,0,0,0,0,0};

// ---------------- helpers ----------------
__device__ __forceinline__ uint32_t smem_u32(const void* p) {
    uint32_t a;
    asm("{ .reg .u64 t; cvta.to.shared.u64 t, %1; cvt.u32.u64 %0, t; }"
        : "=r"(a) : "l"(p));
    return a;
}
#define LDSM4(r, addr) \
    asm volatile("ldmatrix.sync.aligned.m8n8.x4.shared.b16 {%0,%1,%2,%3}, [%4];" \
        : "=r"((r)[0]), "=r"((r)[1]), "=r"((r)[2]), "=r"((r)[3]) : "r"(addr))
#define MMA_BF16(d, a, b0, b1) \
    asm volatile("mma.sync.aligned.m16n8k16.row.col.f32.bf16.bf16.f32 " \
        "{%0,%1,%2,%3}, {%4,%5,%6,%7}, {%8,%9}, {%0,%1,%2,%3};" \
        : "+f"((d)[0]), "+f"((d)[1]), "+f"((d)[2]), "+f"((d)[3]) \
        : "r"((a)[0]), "r"((a)[1]), "r"((a)[2]), "r"((a)[3]), "r"(b0), "r"(b1))
#define CP16(dst, src) \
    asm volatile("cp.async.cg.shared.global [%0], [%1], 16;" :: "r"(dst), "l"(src))
#define CP_COMMIT() asm volatile("cp.async.commit_group;" ::: "memory")
#define CP_WAIT0()  asm volatile("cp.async.wait_group 0;" ::: "memory")

// ============================================================================
// combined split kernel
// ============================================================================
__device__ __forceinline__ void split_store4(float4 v, __nv_bfloat16* hi,
                                             __nv_bfloat16* lo, size_t i4) {
    float vv[4] = {v.x, v.y, v.z, v.w};
    __nv_bfloat16 h[4], l[4];
#pragma unroll
    for (int k = 0; k < 4; k++) {
        h[k] = __float2bfloat16(vv[k]);
        l[k] = __float2bfloat16(vv[k] - __bfloat162float(h[k]));
    }
    ((__nv_bfloat162*)hi)[2 * i4]     = __nv_bfloat162(h[0], h[1]);
    ((__nv_bfloat162*)hi)[2 * i4 + 1] = __nv_bfloat162(h[2], h[3]);
    ((__nv_bfloat162*)lo)[2 * i4]     = __nv_bfloat162(l[0], l[1]);
    ((__nv_bfloat162*)lo)[2 * i4 + 1] = __nv_bfloat162(l[2], l[3]);
}

#define X4   ((size_t)NTOK * DMODEL / 4)
#define W14  ((size_t)4096 * DMODEL / 4)
#define W24  ((size_t)DMODEL * 2048 / 4)
#define BD4  ((size_t)256 * 128 / 4)

__global__ void __launch_bounds__(256) split_all(
    const float* __restrict__ x,  const float* __restrict__ wq,
    const float* __restrict__ ipw, const float* __restrict__ wo,
    const float* __restrict__ aow, const float* __restrict__ sub_keys)
{
    size_t i = (size_t)blockIdx.x * 256 + threadIdx.x;
    if (i < X4) {
        split_store4(((const float4*)x)[i], g_x_hi, g_x_lo, i);
    } else if (i < X4 + W14) {
        size_t j = i - X4;
        const size_t cut = (size_t)1024 * 1024 / 4;
        float4 v = (j < cut) ? ((const float4*)wq)[j] : ((const float4*)ipw)[j - cut];
        split_store4(v, g_w1_hi, g_w1_lo, j);
    } else if (i < X4 + W14 + W24) {
        size_t j = i - X4 - W14;
        int row = (int)(j >> 9);
        int c4  = (int)(j & 511);
        float4 v = (c4 < 256) ? ((const float4*)wo)[row * 256 + c4]
                              : ((const float4*)aow)[row * 256 + c4 - 256];
        split_store4(v, g_w2_hi, g_w2_lo, j);
    } else {
        size_t j = i - X4 - W14 - W24;       // block-diag sub_keys (256 x 128)
        int row = (int)(j >> 5);             // 32 float4 per row
        int c4  = (int)(j & 31);
        float4 v = make_float4(0.f, 0.f, 0.f, 0.f);
        if (row < 128 && c4 < 16)
            v = ((const float4*)sub_keys)[row * 16 + c4];
        else if (row >= 128 && c4 >= 16)
            v = ((const float4*)(sub_keys + 128 * 64))[(row - 128) * 16 + (c4 - 16)];
        split_store4(v, g_bd_hi, g_bd_lo, j);
    }
}

// ============================================================================
// bf16-split "3M" GEMM. CTA tile (32*MT) x 128, warp tile (16*MT) x 32.
// 2-stage cp.async pipeline, 2 CTAs/SM.
// mode 0: col<ncut -> BN((acc+biasA)[col]) and also emit bf16 hi/lo to qh/ql;
//         col>=ncut -> acc + biasB[col-ncut]
// mode 1: acc + biasA[col] + biasB[col]
// mode 2: acc (no bias)
// ============================================================================
template<int MT>
__global__ void __launch_bounds__(256, 2) gemm_mma(
    const __nv_bfloat16* __restrict__ Ahi, const __nv_bfloat16* __restrict__ Alo,
    const __nv_bfloat16* __restrict__ Bhi, const __nv_bfloat16* __restrict__ Blo,
    const float* __restrict__ biasA, const float* __restrict__ biasB,
    const float* __restrict__ bn_mean, const float* __restrict__ bn_var,
    const float* __restrict__ bn_w, const float* __restrict__ bn_b,
    __nv_bfloat16* __restrict__ qh, __nv_bfloat16* __restrict__ ql,
    int mode,
    float* __restrict__ C0, int ld0, float* __restrict__ C1, int ld1, int ncut,
    int K)
{
    constexpr int CM   = 32 * MT;
    constexpr int A_T  = CM * 80;
    constexpr int B_T  = 128 * 80;
    constexpr int STG  = 2 * A_T + 2 * B_T;

    extern __shared__ char smc[];
    uint32_t base = smem_u32(smc);
    int t = threadIdx.x, warp = t >> 5, lane = t & 31;
    int m0 = blockIdx.y * CM, n0 = blockIdx.x * 128;
    int wm = warp >> 2, wn = warp & 3;

    float acc[MT][4][4];
#pragma unroll
    for (int i = 0; i < MT; i++)
#pragma unroll
        for (int j = 0; j < 4; j++)
#pragma unroll
            for (int r = 0; r < 4; r++) acc[i][j][r] = 0.f;

    const int niter = K >> 5;

    auto issue = [&](int it) {
        uint32_t sb = base + (it & 1) * STG;
        int k0 = it << 5;
#pragma unroll
        for (int p = 0; p < CM / 64; p++) {
            int c = t + p * 256;
            int row = c >> 2, j = c & 3;
            const __nv_bfloat16* sh = Ahi + (size_t)(m0 + row) * K + k0 + j * 8;
            const __nv_bfloat16* sl = Alo + (size_t)(m0 + row) * K + k0 + j * 8;
            uint32_t d = sb + (uint32_t)(row * 80 + j * 16);
            CP16(d, sh);
            CP16(d + A_T, sl);
        }
#pragma unroll
        for (int p = 0; p < 2; p++) {
            int c = t + p * 256;
            int row = c >> 2, j = c & 3;
            const __nv_bfloat16* sh = Bhi + (size_t)(n0 + row) * K + k0 + j * 8;
            const __nv_bfloat16* sl = Blo + (size_t)(n0 + row) * K + k0 + j * 8;
            uint32_t d = sb + 2 * A_T + (uint32_t)(row * 80 + j * 16);
            CP16(d, sh);
            CP16(d + B_T, sl);
        }
    };

    issue(0); CP_COMMIT();

    uint32_t a_off = (uint32_t)((wm * (16 * MT) + (lane & 15)) * 80 + (lane >> 4) * 16);
    uint32_t b_off = (uint32_t)((wn * 32 + (lane & 15)) * 80 + (lane >> 4) * 16);

    for (int it = 0; it < niter; ++it) {
        CP_WAIT0();
        __syncthreads();
        if (it + 1 < niter) { issue(it + 1); CP_COMMIT(); }

        uint32_t sb = base + (it & 1) * STG;
        uint32_t sa_h = sb, sa_l = sb + A_T;
        uint32_t sb_h = sb + 2 * A_T, sb_l = sb + 2 * A_T + B_T;

#pragma unroll
        for (int ks = 0; ks < 2; ks++) {
            uint32_t kb = ks * 32;
            uint32_t ah[MT][4], al[MT][4], bh[2][4], bl[2][4];
#pragma unroll
            for (int mt = 0; mt < MT; mt++) {
                uint32_t o = a_off + mt * 16 * 80 + kb;
                LDSM4(ah[mt], sa_h + o);
                LDSM4(al[mt], sa_l + o);
            }
#pragma unroll
            for (int bt = 0; bt < 2; bt++) {
                uint32_t o = b_off + bt * 16 * 80 + kb;
                LDSM4(bh[bt], sb_h + o);
                LDSM4(bl[bt], sb_l + o);
            }
#pragma unroll
            for (int mt = 0; mt < MT; mt++)
#pragma unroll
                for (int nt = 0; nt < 4; nt++)
                    MMA_BF16(acc[mt][nt], ah[mt], bh[nt >> 1][nt & 1], bh[nt >> 1][(nt & 1) + 2]);
#pragma unroll
            for (int mt = 0; mt < MT; mt++)
#pragma unroll
                for (int nt = 0; nt < 4; nt++)
                    MMA_BF16(acc[mt][nt], al[mt], bh[nt >> 1][nt & 1], bh[nt >> 1][(nt & 1) + 2]);
#pragma unroll
            for (int mt = 0; mt < MT; mt++)
#pragma unroll
                for (int nt = 0; nt < 4; nt++)
                    MMA_BF16(acc[mt][nt], ah[mt], bl[nt >> 1][nt & 1], bl[nt >> 1][(nt & 1) + 2]);
        }
    }

    // ---- epilogue ----
    int g = lane >> 2, c2 = lane & 3;
#pragma unroll
    for (int mt = 0; mt < MT; mt++) {
#pragma unroll
        for (int nt = 0; nt < 4; nt++) {
            int row = m0 + wm * (16 * MT) + mt * 16 + g;
            int col = n0 + wn * 32 + nt * 8 + 2 * c2;
            float v[4] = {acc[mt][nt][0], acc[mt][nt][1], acc[mt][nt][2], acc[mt][nt][3]};
            if (mode == 0) {
                if (col < ncut) {
                    float sc0 = rsqrtf(bn_var[col] + 1e-5f) * bn_w[col];
                    float sc1 = rsqrtf(bn_var[col + 1] + 1e-5f) * bn_w[col + 1];
                    float of0 = (biasA[col] - bn_mean[col]) * sc0 + bn_b[col];
                    float of1 = (biasA[col + 1] - bn_mean[col + 1]) * sc1 + bn_b[col + 1];
                    v[0] = v[0] * sc0 + of0; v[1] = v[1] * sc1 + of1;
                    v[2] = v[2] * sc0 + of0; v[3] = v[3] * sc1 + of1;
                    // emit bf16 hi/lo of BN'd q
#pragma unroll
                    for (int rr = 0; rr < 2; rr++) {
                        size_t qi = (size_t)(row + rr * 8) * 1024 + col;
                        __nv_bfloat16 h0 = __float2bfloat16(v[2 * rr]);
                        __nv_bfloat16 h1 = __float2bfloat16(v[2 * rr + 1]);
                        *(__nv_bfloat162*)(qh + qi) = __nv_bfloat162(h0, h1);
                        *(__nv_bfloat162*)(ql + qi) = __nv_bfloat162(
                            __float2bfloat16(v[2 * rr] - __bfloat162float(h0)),
                            __float2bfloat16(v[2 * rr + 1] - __bfloat162float(h1)));
                    }
                } else {
                    float b0 = biasB[col - ncut], b1 = biasB[col + 1 - ncut];
                    v[0] += b0; v[1] += b1; v[2] += b0; v[3] += b1;
                }
            } else if (mode == 1) {
                float b0 = biasA[col] + biasB[col];
                float b1 = biasA[col + 1] + biasB[col + 1];
                v[0] += b0; v[1] += b1; v[2] += b0; v[3] += b1;
            }
            float* C; int ld, cc;
            if (col < ncut) { C = C0; ld = ld0; cc = col; }
            else            { C = C1; ld = ld1; cc = col - ncut; }
            *(float2*)(C + (size_t)row * ld + cc)       = make_float2(v[0], v[1]);
            *(float2*)(C + (size_t)(row + 8) * ld + cc) = make_float2(v[2], v[3]);
        }
    }
}

// ============================================================================
// PEER routing: reads precomputed scores g_s + BN'd q; 50-candidate top-16
// ============================================================================
__global__ void __launch_bounds__(128) peer_route(const float* __restrict__ expert_w)
{
    int row   = blockIdx.x;          // token*8 + head
    int token = row >> 3;
    int head  = row & 7;
    int tid   = threadIdx.x;

    __shared__ float q[128];
    __shared__ float sh1[128], sh2[128];
    __shared__ float v1[16], v2[16];
    __shared__ int   i1[16], i2[16];
    __shared__ float cv[50];
    __shared__ int   ci[50];
    __shared__ int   sel[16];
    __shared__ float simv[16];
    __shared__ float rw[16];
    __shared__ float ews[16][128];

    q[tid] = g_q[(size_t)token * HK + head * 128 + tid];
    float s1v = g_s[(size_t)row * 256 + tid];
    float s2v = g_s[(size_t)row * 256 + 128 + tid];
    sh1[tid] = s1v; sh2[tid] = s2v;
    __syncthreads();

    // full rank of own value in each 128-vector (desc, index tiebreak)
    int r1 = 0, r2 = 0;
#pragma unroll 8
    for (int j = 0; j < 128; j++) {
        float w1 = sh1[j]; r1 += (w1 > s1v) || (w1 == s1v && j < tid);
        float w2 = sh2[j]; r2 += (w2 > s2v) || (w2 == s2v && j < tid);
    }
    if (r1 < 16) { v1[r1] = s1v; i1[r1] = tid; }
    if (r2 < 16) { v2[r2] = s2v; i2[r2] = tid; }
    __syncthreads();

    // 50 dominance-pruned candidates; rank-select top 16
    if (tid < 50) {
        int a = CAND_A[tid], b = CAND_B[tid];
        cv[tid] = v1[a] + v2[b];
        ci[tid] = i1[a] * NSUB + i2[b];
    }
    __syncthreads();
    if (tid < 50) {
        float v = cv[tid];
        int r = 0;
#pragma unroll 10
        for (int j = 0; j < 50; j++) {
            float w = cv[j];
            r += (w > v) || (w == v && j < tid);
        }
        if (r < 16) sel[r] = ci[tid];
    }
    __syncthreads();

    // gather expert rows
#pragma unroll
    for (int k = 0; k < 16; k++)
        ews[k][tid] = expert_w[(size_t)sel[k] * DKEY + tid];
    __syncthreads();

    // sim_k = dot(q, ews[k]); 8 lanes per expert
    int k8 = tid >> 3, l8 = tid & 7;
    float part = 0.f;
#pragma unroll
    for (int i = 0; i < 16; i++) {
        int d = l8 * 16 + i;
        part += q[d] * ews[k8][d];
    }
    part += __shfl_down_sync(0xffffffffu, part, 4);
    part += __shfl_down_sync(0xffffffffu, part, 2);
    part += __shfl_down_sync(0xffffffffu, part, 1);
    if (l8 == 0) simv[k8] = part;
    __syncthreads();

    if (tid == 0) {
        float m = -INFINITY;
#pragma unroll
        for (int k = 0; k < 16; k++) m = fmaxf(m, simv[k]);
        float e[16]; float s = 0.f;
#pragma unroll
        for (int k = 0; k < 16; k++) { e[k] = expf(simv[k] - m); s += e[k]; }
        float inv = 1.f / s;
#pragma unroll
        for (int k = 0; k < 16; k++) rw[k] = e[k] * inv;
    }
    __syncthreads();

    float o = 0.f;
#pragma unroll
    for (int k = 0; k < 16; k++) o += rw[k] * ews[k][tid];
    size_t idx = (size_t)token * 2048 + head * 128 + tid;
    __nv_bfloat16 h = __float2bfloat16(o);
    g_cat_hi[idx] = h;
    g_cat_lo[idx] = __float2bfloat16(o - __bfloat162float(h));
}

// ============================================================================
// Attention scores + softmax
// ============================================================================
__global__ void __launch_bounds__(256) attn_scores()
{
    int z = blockIdx.y;
    int b = z >> 3, h = z & 7;
    int q0 = blockIdx.x * 16;
    int t = threadIdx.x;

    __shared__ float qs[16][128];
    __shared__ float Ks[32][132];

#pragma unroll
    for (int s = 0; s < 2; s++) {
        int v = t + s * 256;
        int r = v >> 5, c4 = (v & 31) * 4;
        float4 val = *(const float4*)&g_qkv[(size_t)(b * TSEQ + q0 + r) * (3 * DMODEL) + h * HD + c4];
        *(float4*)&qs[r][c4] = val;
    }
    __syncthreads();

    int j  = t & 15;
    int rr = t >> 4;
    float sreg[32];

    for (int kt = 0; kt < 16; kt++) {
#pragma unroll
        for (int s = 0; s < 4; s++) {
            int v = t + s * 256;
            int kr = v >> 5, c4 = (v & 31) * 4;
            float4 val = *(const float4*)&g_qkv[(size_t)(b * TSEQ + kt * 32 + kr) * (3 * DMODEL) + DMODEL + h * HD + c4];
            Ks[kr][c4 + 0] = val.x; Ks[kr][c4 + 1] = val.y;
            Ks[kr][c4 + 2] = val.z; Ks[kr][c4 + 3] = val.w;
        }
        __syncthreads();
        float acc1 = 0.f, acc2 = 0.f;
        const float4* qr  = (const float4*)&qs[rr][0];
        const float4* ka4 = (const float4*)&Ks[j][0];
        const float4* kb4 = (const float4*)&Ks[j + 16][0];
#pragma unroll
        for (int i = 0; i < 32; i++) {
            float4 qv = qr[i];
            float4 a  = ka4[i];
            float4 bb = kb4[i];
            acc1 += qv.x * a.x + qv.y * a.y + qv.z * a.z + qv.w * a.w;
            acc2 += qv.x * bb.x + qv.y * bb.y + qv.z * bb.z + qv.w * bb.w;
        }
        sreg[2 * kt]     = acc1;
        sreg[2 * kt + 1] = acc2;
        __syncthreads();
    }

    const float scale = 0.08838834764831845f;
#pragma unroll
    for (int i = 0; i < 32; i++) sreg[i] *= scale;

    float m = -INFINITY;
#pragma unroll
    for (int i = 0; i < 32; i++) m = fmaxf(m, sreg[i]);
#pragma unroll
    for (int off = 8; off; off >>= 1)
        m = fmaxf(m, __shfl_xor_sync(0xffffffffu, m, off));
    float sum = 0.f;
#pragma unroll
    for (int i = 0; i < 32; i++) { sreg[i] = expf(sreg[i] - m); sum += sreg[i]; }
#pragma unroll
    for (int off = 8; off; off >>= 1)
        sum += __shfl_xor_sync(0xffffffffu, sum, off);
    float inv = 1.f / sum;

    float* arow = g_att + ((size_t)z * TSEQ + q0 + rr) * TSEQ;
#pragma unroll
    for (int kt = 0; kt < 16; kt++) {
        arow[kt * 32 + j]      = sreg[2 * kt] * inv;
        arow[kt * 32 + 16 + j] = sreg[2 * kt + 1] * inv;
    }
}

// ============================================================================
// AV GEMM (SIMT) -> writes bf16 hi/lo into cat cols [1024,2048)
// ============================================================================
__global__ void __launch_bounds__(256) gemm_av()
{
    int z = blockIdx.z;
    int b = z >> 3, h = z & 7;
    const float* A  = g_att + (size_t)z * TSEQ * TSEQ;
    const float* Bb = g_qkv + (size_t)b * TSEQ * (3 * DMODEL) + 2 * DMODEL + h * HD;

    __shared__ float As[16][128];
    __shared__ float Bs[16][64];
    int t  = threadIdx.x;
    int m0 = blockIdx.y * 128;
    int n0 = blockIdx.x * 64;
    int tx = t & 15, ty = t >> 4;

    float acc[8][4];
#pragma unroll
    for (int i = 0; i < 8; i++)
#pragma unroll
        for (int j = 0; j < 4; j++) acc[i][j] = 0.f;

    for (int k0 = 0; k0 < TSEQ; k0 += 16) {
#pragma unroll
        for (int s = 0; s < 2; s++) {
            int v = t + s * 256;
            int row = v >> 2, c4 = (v & 3) * 4;
            float4 a = *(const float4*)(A + (size_t)(m0 + row) * TSEQ + k0 + c4);
            As[c4 + 0][row] = a.x; As[c4 + 1][row] = a.y;
            As[c4 + 2][row] = a.z; As[c4 + 3][row] = a.w;
        }
        {
            int kr = t >> 4, c4 = (t & 15) * 4;
            float4 bv = *(const float4*)(Bb + (size_t)(k0 + kr) * (3 * DMODEL) + n0 + c4);
            *(float4*)&Bs[kr][c4] = bv;
        }
        __syncthreads();
#pragma unroll
        for (int kk = 0; kk < 16; kk++) {
            float ar[8], br[4];
#pragma unroll
            for (int i = 0; i < 8; i++) ar[i] = As[kk][ty * 8 + i];
#pragma unroll
            for (int jj = 0; jj < 4; jj++) br[jj] = Bs[kk][tx * 4 + jj];
#pragma unroll
            for (int i = 0; i < 8; i++)
#pragma unroll
                for (int jj = 0; jj < 4; jj++) acc[i][jj] += ar[i] * br[jj];
        }
        __syncthreads();
    }
#pragma unroll
    for (int i = 0; i < 8; i++) {
        int m = m0 + ty * 8 + i;
        int token = b * TSEQ + m;
#pragma unroll
        for (int jj = 0; jj < 4; jj++) {
            float v = acc[i][jj];
            size_t idx = (size_t)token * 2048 + 1024 + h * HD + n0 + tx * 4 + jj;
            __nv_bfloat16 hh = __float2bfloat16(v);
            g_cat_hi[idx] = hh;
            g_cat_lo[idx] = __float2bfloat16(v - __bfloat162float(hh));
        }
    }
}

// mean over heads
__global__ void __launch_bounds__(256) attn_mean(float* __restrict__ out)
{
    int idx = blockIdx.x * 256 + threadIdx.x;
    int b   = idx / (TSEQ * TSEQ);
    int rem = idx - b * (TSEQ * TSEQ);
    float s = 0.f;
#pragma unroll
    for (int h = 0; h < 8; h++)
        s += g_att[((size_t)(b * 8 + h)) * (TSEQ * TSEQ) + rem];
    out[idx] = s * 0.125f;
}

// y = rmsnorm(x + g_sum) * rms_w
__global__ void __launch_bounds__(256) final_rms(
    const float* __restrict__ x, const float* __restrict__ rms_w,
    float* __restrict__ y)
{
    int token = blockIdx.x;
    int t = threadIdx.x;
    size_t base = (size_t)token * DMODEL;
    float v[4];
    float ss = 0.f;
#pragma unroll
    for (int u = 0; u < 4; u++) {
        int c = t + u * 256;
        float s = x[base + c] + g_sum[base + c];
        v[u] = s;
        ss += s * s;
    }
#pragma unroll
    for (int off = 16; off; off >>= 1)
        ss += __shfl_xor_sync(0xffffffffu, ss, off);
    __shared__ float red[8];
    __shared__ float stot;
    if ((t & 31) == 0) red[t >> 5] = ss;
    __syncthreads();
    if (t == 0) {
        float s = 0.f;
#pragma unroll
        for (int i = 0; i < 8; i++) s += red[i];
        stot = rsqrtf(s * (1.f / DMODEL) + 1e-6f);
    }
    __syncthreads();
    float inv = stot;
#pragma unroll
    for (int u = 0; u < 4; u++) {
        int c = t + u * 256;
        y[base + c] = v[u] * inv * rms_w[c];
    }
}

// ============================================================================
extern "C" void kernel_launch(void* const* d_in, const int* in_sizes, int n_in,
                              void* d_out, int out_size)
{
    const float* x         = (const float*)d_in[0];
    const float* wq        = (const float*)d_in[1];
    const float* bq        = (const float*)d_in[2];
    const float* bn_w      = (const float*)d_in[3];
    const float* bn_b      = (const float*)d_in[4];
    const float* bn_mean   = (const float*)d_in[5];
    const float* bn_var    = (const float*)d_in[6];
    const float* sub_keys  = (const float*)d_in[7];
    const float* expert_w  = (const float*)d_in[8];
    const float* wo        = (const float*)d_in[9];
    const float* bo        = (const float*)d_in[10];
    const float* in_proj_w = (const float*)d_in[11];
    const float* in_proj_b = (const float*)d_in[12];
    const float* attn_ow   = (const float*)d_in[13];
    const float* attn_ob   = (const float*)d_in[14];
    const float* rms_w     = (const float*)d_in[15];

    float* y      = (float*)d_out;
    float* attn_w = (float*)d_out + (size_t)NTOK * DMODEL;

    void *p_q, *p_qkv, *p_sum, *p_s;
    cudaGetSymbolAddress(&p_q, g_q);
    cudaGetSymbolAddress(&p_qkv, g_qkv);
    cudaGetSymbolAddress(&p_sum, g_sum);
    cudaGetSymbolAddress(&p_s, g_s);

    void *xh, *xl, *w1h, *w1l, *w2h, *w2l, *ch, *cl, *qbh, *qbl, *bdh, *bdl;
    cudaGetSymbolAddress(&xh,  g_x_hi);  cudaGetSymbolAddress(&xl,  g_x_lo);
    cudaGetSymbolAddress(&w1h, g_w1_hi); cudaGetSymbolAddress(&w1l, g_w1_lo);
    cudaGetSymbolAddress(&w2h, g_w2_hi); cudaGetSymbolAddress(&w2l, g_w2_lo);
    cudaGetSymbolAddress(&ch,  g_cat_hi); cudaGetSymbolAddress(&cl, g_cat_lo);
    cudaGetSymbolAddress(&qbh, g_qbn_hi); cudaGetSymbolAddress(&qbl, g_qbn_lo);
    cudaGetSymbolAddress(&bdh, g_bd_hi); cudaGetSymbolAddress(&bdl, g_bd_lo);

    constexpr int SMEM4 = 2 * (2 * 128 * 80 + 2 * 128 * 80);  // 81920
    constexpr int SMEM2 = 2 * (2 * 64 * 80 + 2 * 128 * 80);   // 61440
    cudaFuncSetAttribute(gemm_mma<4>, cudaFuncAttributeMaxDynamicSharedMemorySize, SMEM4);
    cudaFuncSetAttribute(gemm_mma<2>, cudaFuncAttributeMaxDynamicSharedMemorySize, SMEM2);

    // [0] combined split (+ blockdiag sub_keys)
    split_all<<<(int)((X4 + W14 + W24 + BD4) / 256), 256>>>(
        x, wq, in_proj_w, wo, attn_ow, sub_keys);

    // [1] fused q+qkv GEMM with BN epilogue on q part (also emits q bf16 hi/lo)
    gemm_mma<4><<<dim3(4096 / 128, NTOK / 128), 256, SMEM4>>>(
        (const __nv_bfloat16*)xh, (const __nv_bfloat16*)xl,
        (const __nv_bfloat16*)w1h, (const __nv_bfloat16*)w1l,
        bq, in_proj_b, bn_mean, bn_var, bn_w, bn_b,
        (__nv_bfloat16*)qbh, (__nv_bfloat16*)qbl, 0,
        (float*)p_q, HK, (float*)p_qkv, 3 * DMODEL, 1024, DMODEL);

    // [2] sub-key scores: q_bn(8192x128) @ blockdiag(256x128)^T -> g_s
    gemm_mma<4><<<dim3(256 / 128, 8192 / 128), 256, SMEM4>>>(
        (const __nv_bfloat16*)qbh, (const __nv_bfloat16*)qbl,
        (const __nv_bfloat16*)bdh, (const __nv_bfloat16*)bdl,
        bq, bq, bn_mean, bn_var, bn_w, bn_b, nullptr, nullptr, 2,
        (float*)p_s, 256, (float*)p_s, 256, 1 << 30, 128);

    // [3] PEER routing  <- ncu capture slot
    peer_route<<<NTOK * NHEADS, 128>>>(expert_w);

    // [4..6] attention
    attn_scores<<<dim3(TSEQ / 16, BATCH * NHEADS), 256>>>();
    gemm_av<<<dim3(HD / 64, TSEQ / 128, BATCH * NHEADS), 256>>>();
    attn_mean<<<(BATCH * TSEQ * TSEQ) / 256, 256>>>(attn_w);

    // [7] fused output projection
    gemm_mma<2><<<dim3(DMODEL / 128, NTOK / 64), 256, SMEM2>>>(
        (const __nv_bfloat16*)ch, (const __nv_bfloat16*)cl,
        (const __nv_bfloat16*)w2h, (const __nv_bfloat16*)w2l,
        bo, attn_ob, bn_mean, bn_var, bn_w, bn_b, nullptr, nullptr, 1,
        (float*)p_sum, DMODEL, (float*)p_sum, DMODEL, 1 << 30, 2048);

    // [8] residual + rmsnorm
    final_rms<<<NTOK, 256>>>(x, rms_w, y);

    (void)in_sizes; (void)n_in; (void)out_size;
}

// round 9
// speedup vs baseline: 3.0281x; 1.3182x over previous
#include <cuda_runtime.h>
#include <cuda_bf16.h>
#include <math.h>
#include <stdint.h>

// ---------------- problem constants ----------------
#define BATCH   2
#define TSEQ    512
#define NTOK    1024
#define DMODEL  1024
#define NHEADS  8
#define DKEY    128
#define HK      1024
#define NSUB    128
#define TOPK    16
#define HD      128
#define NZ      16        // BATCH*NHEADS

// ---------------- scratch ----------------
__device__ __align__(128) float g_q[NTOK * HK];          // BN'd q (fp32)
__device__ __align__(128) float g_qkv[NTOK * 3 * DMODEL];
__device__ __align__(128) float g_att[NZ * TSEQ * TSEQ];   // raw scores -> probs
__device__ __align__(128) float g_sum[NTOK * DMODEL];
__device__ __align__(128) float g_s[NTOK * NHEADS * 256];  // sub-key scores

__device__ __align__(128) __nv_bfloat16 g_x_hi[NTOK * DMODEL],  g_x_lo[NTOK * DMODEL];
__device__ __align__(128) __nv_bfloat16 g_w1_hi[4096 * DMODEL], g_w1_lo[4096 * DMODEL];
__device__ __align__(128) __nv_bfloat16 g_w2_hi[DMODEL * 2048], g_w2_lo[DMODEL * 2048];
__device__ __align__(128) __nv_bfloat16 g_cat_hi[NTOK * 2048],  g_cat_lo[NTOK * 2048];
__device__ __align__(128) __nv_bfloat16 g_qbn_hi[NTOK * HK],    g_qbn_lo[NTOK * HK];
__device__ __align__(128) __nv_bfloat16 g_bd_hi[256 * 128],     g_bd_lo[256 * 128];
// attention bf16 operands, per-head contiguous [z][t][d] / [z][e][k]
__device__ __align__(128) __nv_bfloat16 g_qa_hi[NZ * TSEQ * HD], g_qa_lo[NZ * TSEQ * HD];
__device__ __align__(128) __nv_bfloat16 g_ka_hi[NZ * TSEQ * HD], g_ka_lo[NZ * TSEQ * HD];
__device__ __align__(128) __nv_bfloat16 g_p_hi[NZ * TSEQ * TSEQ], g_p_lo[NZ * TSEQ * TSEQ];
__device__ __align__(128) __nv_bfloat16 g_vt_hi[NZ * HD * TSEQ],  g_vt_lo[NZ * HD * TSEQ];

// 50 candidates (a,b) with (a+1)(b+1) <= 16 over rank-sorted v1,v2
__device__ const int CAND_A[50] = {0,0,0,0,0,0,0,0,0,0,0,0,0,0,0,0,
                                   1,1,1,1,1,1,1,1, 2,2,2,2,2, 3,3,3,3,
                                   4,4,4, 5,5, 6,6, 7,7, 8,9,10,11,12,13,14,15};
__device__ const int CAND_B[50] = {0,1,2,3,4,5,6,7,8,9,10,11,12,13,14,15,
                                   0,1,2,3,4,5,6,7, 0,1,2,3,4, 0,1,2,3,
                                   0,1,2, 0,1, 0,1, 0,1, 0,0,0,0,0,0,0,0};

// ---------------- helpers ----------------
__device__ __forceinline__ uint32_t smem_u32(const void* p) {
    uint32_t a;
    asm("{ .reg .u64 t; cvta.to.shared.u64 t, %1; cvt.u32.u64 %0, t; }"
        : "=r"(a) : "l"(p));
    return a;
}
#define LDSM4(r, addr) \
    asm volatile("ldmatrix.sync.aligned.m8n8.x4.shared.b16 {%0,%1,%2,%3}, [%4];" \
        : "=r"((r)[0]), "=r"((r)[1]), "=r"((r)[2]), "=r"((r)[3]) : "r"(addr))
#define MMA_BF16(d, a, b0, b1) \
    asm volatile("mma.sync.aligned.m16n8k16.row.col.f32.bf16.bf16.f32 " \
        "{%0,%1,%2,%3}, {%4,%5,%6,%7}, {%8,%9}, {%0,%1,%2,%3};" \
        : "+f"((d)[0]), "+f"((d)[1]), "+f"((d)[2]), "+f"((d)[3]) \
        : "r"((a)[0]), "r"((a)[1]), "r"((a)[2]), "r"((a)[3]), "r"(b0), "r"(b1))
#define CP16(dst, src) \
    asm volatile("cp.async.cg.shared.global [%0], [%1], 16;" :: "r"(dst), "l"(src))
#define CP_COMMIT() asm volatile("cp.async.commit_group;" ::: "memory")
#define CP_WAIT0()  asm volatile("cp.async.wait_group 0;" ::: "memory")

__device__ __forceinline__ void bf16x2_split_store(__nv_bfloat16* hi, __nv_bfloat16* lo,
                                                   size_t idx, float a, float b) {
    __nv_bfloat16 h0 = __float2bfloat16(a);
    __nv_bfloat16 h1 = __float2bfloat16(b);
    *(__nv_bfloat162*)(hi + idx) = __nv_bfloat162(h0, h1);
    *(__nv_bfloat162*)(lo + idx) = __nv_bfloat162(
        __float2bfloat16(a - __bfloat162float(h0)),
        __float2bfloat16(b - __bfloat162float(h1)));
}

// ============================================================================
// combined split kernel
// ============================================================================
__device__ __forceinline__ void split_store4(float4 v, __nv_bfloat16* hi,
                                             __nv_bfloat16* lo, size_t i4) {
    float vv[4] = {v.x, v.y, v.z, v.w};
    __nv_bfloat16 h[4], l[4];
#pragma unroll
    for (int k = 0; k < 4; k++) {
        h[k] = __float2bfloat16(vv[k]);
        l[k] = __float2bfloat16(vv[k] - __bfloat162float(h[k]));
    }
    ((__nv_bfloat162*)hi)[2 * i4]     = __nv_bfloat162(h[0], h[1]);
    ((__nv_bfloat162*)hi)[2 * i4 + 1] = __nv_bfloat162(h[2], h[3]);
    ((__nv_bfloat162*)lo)[2 * i4]     = __nv_bfloat162(l[0], l[1]);
    ((__nv_bfloat162*)lo)[2 * i4 + 1] = __nv_bfloat162(l[2], l[3]);
}

#define X4   ((size_t)NTOK * DMODEL / 4)
#define W14  ((size_t)4096 * DMODEL / 4)
#define W24  ((size_t)DMODEL * 2048 / 4)
#define BD4  ((size_t)256 * 128 / 4)

__global__ void __launch_bounds__(256) split_all(
    const float* __restrict__ x,  const float* __restrict__ wq,
    const float* __restrict__ ipw, const float* __restrict__ wo,
    const float* __restrict__ aow, const float* __restrict__ sub_keys)
{
    size_t i = (size_t)blockIdx.x * 256 + threadIdx.x;
    if (i < X4) {
        split_store4(((const float4*)x)[i], g_x_hi, g_x_lo, i);
    } else if (i < X4 + W14) {
        size_t j = i - X4;
        const size_t cut = (size_t)1024 * 1024 / 4;
        float4 v = (j < cut) ? ((const float4*)wq)[j] : ((const float4*)ipw)[j - cut];
        split_store4(v, g_w1_hi, g_w1_lo, j);
    } else if (i < X4 + W14 + W24) {
        size_t j = i - X4 - W14;
        int row = (int)(j >> 9);
        int c4  = (int)(j & 511);
        float4 v = (c4 < 256) ? ((const float4*)wo)[row * 256 + c4]
                              : ((const float4*)aow)[row * 256 + c4 - 256];
        split_store4(v, g_w2_hi, g_w2_lo, j);
    } else {
        size_t j = i - X4 - W14 - W24;       // block-diag sub_keys (256 x 128)
        int row = (int)(j >> 5);
        int c4  = (int)(j & 31);
        float4 v = make_float4(0.f, 0.f, 0.f, 0.f);
        if (row < 128 && c4 < 16)
            v = ((const float4*)sub_keys)[row * 16 + c4];
        else if (row >= 128 && c4 >= 16)
            v = ((const float4*)(sub_keys + 128 * 64))[(row - 128) * 16 + (c4 - 16)];
        split_store4(v, g_bd_hi, g_bd_lo, j);
    }
}

// ============================================================================
// bf16-split "3M" GEMM. CTA tile (32*MT) x 128, warp tile (16*MT) x 32.
// 2-stage cp.async pipeline, 2 CTAs/SM. Batched via blockIdx.z.
// mode 0: gemm1 epilogue: col<1024 -> BN + emit qbn hi/lo;
//         col in [1024,3072) -> +biasB, also emit qa/ka hi/lo per-head layout;
//         col >= 3072 -> +biasB only. fp32 out split at ncut (C0=q, C1=qkv).
// mode 1: acc + biasA + biasB -> fp32 C0
// mode 2: acc -> fp32 C0
// mode 3: acc*scale -> fp32 C0 (batched)
// mode 4: emit bf16 hi/lo into g_cat AV region (batched)
// ============================================================================
template<int MT>
__global__ void __launch_bounds__(256, 2) gemm_mma(
    const __nv_bfloat16* __restrict__ Ahi, const __nv_bfloat16* __restrict__ Alo,
    const __nv_bfloat16* __restrict__ Bhi, const __nv_bfloat16* __restrict__ Blo,
    int lda, int ldb, size_t batchA, size_t batchB,
    const float* __restrict__ biasA, const float* __restrict__ biasB,
    const float* __restrict__ bn_mean, const float* __restrict__ bn_var,
    const float* __restrict__ bn_w, const float* __restrict__ bn_b,
    int mode, float scale,
    float* __restrict__ C0, int ld0, float* __restrict__ C1, int ld1, int ncut,
    size_t batchC, int K)
{
    constexpr int CM   = 32 * MT;
    constexpr int A_T  = CM * 80;
    constexpr int B_T  = 128 * 80;
    constexpr int STG  = 2 * A_T + 2 * B_T;

    extern __shared__ char smc[];
    uint32_t base = smem_u32(smc);
    int t = threadIdx.x, warp = t >> 5, lane = t & 31;
    int m0 = blockIdx.y * CM, n0 = blockIdx.x * 128;
    int z  = blockIdx.z;
    int wm = warp >> 2, wn = warp & 3;

    const __nv_bfloat16* Ah = Ahi + batchA * z;
    const __nv_bfloat16* Al = Alo + batchA * z;
    const __nv_bfloat16* Bh = Bhi + batchB * z;
    const __nv_bfloat16* Bl = Blo + batchB * z;

    float acc[MT][4][4];
#pragma unroll
    for (int i = 0; i < MT; i++)
#pragma unroll
        for (int j = 0; j < 4; j++)
#pragma unroll
            for (int r = 0; r < 4; r++) acc[i][j][r] = 0.f;

    const int niter = K >> 5;

    auto issue = [&](int it) {
        uint32_t sb = base + (it & 1) * STG;
        int k0 = it << 5;
#pragma unroll
        for (int p = 0; p < CM / 64; p++) {
            int c = t + p * 256;
            int row = c >> 2, j = c & 3;
            const __nv_bfloat16* sh = Ah + (size_t)(m0 + row) * lda + k0 + j * 8;
            const __nv_bfloat16* sl = Al + (size_t)(m0 + row) * lda + k0 + j * 8;
            uint32_t d = sb + (uint32_t)(row * 80 + j * 16);
            CP16(d, sh);
            CP16(d + A_T, sl);
        }
#pragma unroll
        for (int p = 0; p < 2; p++) {
            int c = t + p * 256;
            int row = c >> 2, j = c & 3;
            const __nv_bfloat16* sh = Bh + (size_t)(n0 + row) * ldb + k0 + j * 8;
            const __nv_bfloat16* sl = Bl + (size_t)(n0 + row) * ldb + k0 + j * 8;
            uint32_t d = sb + 2 * A_T + (uint32_t)(row * 80 + j * 16);
            CP16(d, sh);
            CP16(d + B_T, sl);
        }
    };

    issue(0); CP_COMMIT();

    uint32_t a_off = (uint32_t)((wm * (16 * MT) + (lane & 15)) * 80 + (lane >> 4) * 16);
    uint32_t b_off = (uint32_t)((wn * 32 + (lane & 15)) * 80 + (lane >> 4) * 16);

    for (int it = 0; it < niter; ++it) {
        CP_WAIT0();
        __syncthreads();
        if (it + 1 < niter) { issue(it + 1); CP_COMMIT(); }

        uint32_t sb = base + (it & 1) * STG;
        uint32_t sa_h = sb, sa_l = sb + A_T;
        uint32_t sb_h = sb + 2 * A_T, sb_l = sb + 2 * A_T + B_T;

#pragma unroll
        for (int ks = 0; ks < 2; ks++) {
            uint32_t kb = ks * 32;
            uint32_t ah[MT][4], al[MT][4], bh[2][4], bl[2][4];
#pragma unroll
            for (int mt = 0; mt < MT; mt++) {
                uint32_t o = a_off + mt * 16 * 80 + kb;
                LDSM4(ah[mt], sa_h + o);
                LDSM4(al[mt], sa_l + o);
            }
#pragma unroll
            for (int bt = 0; bt < 2; bt++) {
                uint32_t o = b_off + bt * 16 * 80 + kb;
                LDSM4(bh[bt], sb_h + o);
                LDSM4(bl[bt], sb_l + o);
            }
#pragma unroll
            for (int mt = 0; mt < MT; mt++)
#pragma unroll
                for (int nt = 0; nt < 4; nt++)
                    MMA_BF16(acc[mt][nt], ah[mt], bh[nt >> 1][nt & 1], bh[nt >> 1][(nt & 1) + 2]);
#pragma unroll
            for (int mt = 0; mt < MT; mt++)
#pragma unroll
                for (int nt = 0; nt < 4; nt++)
                    MMA_BF16(acc[mt][nt], al[mt], bh[nt >> 1][nt & 1], bh[nt >> 1][(nt & 1) + 2]);
#pragma unroll
            for (int mt = 0; mt < MT; mt++)
#pragma unroll
                for (int nt = 0; nt < 4; nt++)
                    MMA_BF16(acc[mt][nt], ah[mt], bl[nt >> 1][nt & 1], bl[nt >> 1][(nt & 1) + 2]);
        }
    }

    // ---- epilogue ----
    int g = lane >> 2, c2 = lane & 3;
#pragma unroll
    for (int mt = 0; mt < MT; mt++) {
#pragma unroll
        for (int nt = 0; nt < 4; nt++) {
            int row = m0 + wm * (16 * MT) + mt * 16 + g;
            int col = n0 + wn * 32 + nt * 8 + 2 * c2;
            float v[4] = {acc[mt][nt][0], acc[mt][nt][1], acc[mt][nt][2], acc[mt][nt][3]};
            if (mode == 4) {
                // AV output: token = (z>>3)*512 + row ; cat col = 1024 + (z&7)*128 + col
#pragma unroll
                for (int rr = 0; rr < 2; rr++) {
                    size_t idx = (size_t)((z >> 3) * 512 + row + rr * 8) * 2048
                               + 1024 + (z & 7) * 128 + col;
                    bf16x2_split_store(g_cat_hi, g_cat_lo, idx, v[2 * rr], v[2 * rr + 1]);
                }
                continue;
            }
            if (mode == 3) {
                v[0] *= scale; v[1] *= scale; v[2] *= scale; v[3] *= scale;
            } else if (mode == 0) {
                if (col < 1024) {
                    float sc0 = rsqrtf(bn_var[col] + 1e-5f) * bn_w[col];
                    float sc1 = rsqrtf(bn_var[col + 1] + 1e-5f) * bn_w[col + 1];
                    float of0 = (biasA[col] - bn_mean[col]) * sc0 + bn_b[col];
                    float of1 = (biasA[col + 1] - bn_mean[col + 1]) * sc1 + bn_b[col + 1];
                    v[0] = v[0] * sc0 + of0; v[1] = v[1] * sc1 + of1;
                    v[2] = v[2] * sc0 + of0; v[3] = v[3] * sc1 + of1;
#pragma unroll
                    for (int rr = 0; rr < 2; rr++)
                        bf16x2_split_store(g_qbn_hi, g_qbn_lo,
                                           (size_t)(row + rr * 8) * 1024 + col,
                                           v[2 * rr], v[2 * rr + 1]);
                } else {
                    float b0 = biasB[col - 1024], b1 = biasB[col + 1 - 1024];
                    v[0] += b0; v[1] += b1; v[2] += b0; v[3] += b1;
                    if (col < 3072) {
                        // qa (col in [1024,2048)) or ka ([2048,3072)): emit per-head
                        int cc   = (col < 2048) ? col - 1024 : col - 2048;
                        int h    = cc >> 7, d = cc & 127;
                        __nv_bfloat16* oh = (col < 2048) ? g_qa_hi : g_ka_hi;
                        __nv_bfloat16* ol = (col < 2048) ? g_qa_lo : g_ka_lo;
#pragma unroll
                        for (int rr = 0; rr < 2; rr++) {
                            int token = row + rr * 8;              // = b*512 + t
                            int zz = (token >> 9) * 8 + h;
                            size_t idx = (size_t)zz * (TSEQ * HD)
                                       + (size_t)(token & 511) * HD + d;
                            bf16x2_split_store(oh, ol, idx, v[2 * rr], v[2 * rr + 1]);
                        }
                    }
                }
            } else if (mode == 1) {
                float b0 = biasA[col] + biasB[col];
                float b1 = biasA[col + 1] + biasB[col + 1];
                v[0] += b0; v[1] += b1; v[2] += b0; v[3] += b1;
            }
            float* C; int ld, cc;
            if (col < ncut) { C = C0; ld = ld0; cc = col; }
            else            { C = C1; ld = ld1; cc = col - ncut; }
            C += batchC * z;
            *(float2*)(C + (size_t)row * ld + cc)       = make_float2(v[0], v[1]);
            *(float2*)(C + (size_t)(row + 8) * ld + cc) = make_float2(v[2], v[3]);
        }
    }
}

// ============================================================================
// softmax over attention score rows; writes probs fp32 + bf16 hi/lo P
// ============================================================================
__global__ void __launch_bounds__(256) attn_softmax()
{
    int row = blockIdx.x;                 // z*512 + q
    float* arow = g_att + (size_t)row * TSEQ;
    int t = threadIdx.x;
    float v0 = arow[t], v1 = arow[t + 256];

    __shared__ float red[8];
    float m = fmaxf(v0, v1);
#pragma unroll
    for (int off = 16; off; off >>= 1)
        m = fmaxf(m, __shfl_xor_sync(0xffffffffu, m, off));
    if ((t & 31) == 0) red[t >> 5] = m;
    __syncthreads();
    if (t < 32) {
        float mm = (t < 8) ? red[t] : -INFINITY;
#pragma unroll
        for (int off = 4; off; off >>= 1)
            mm = fmaxf(mm, __shfl_xor_sync(0xffffffffu, mm, off));
        if (t == 0) red[0] = mm;
    }
    __syncthreads();
    m = red[0];
    __syncthreads();

    float e0 = expf(v0 - m), e1 = expf(v1 - m);
    float s = e0 + e1;
#pragma unroll
    for (int off = 16; off; off >>= 1)
        s += __shfl_xor_sync(0xffffffffu, s, off);
    if ((t & 31) == 0) red[t >> 5] = s;
    __syncthreads();
    if (t < 32) {
        float ss = (t < 8) ? red[t] : 0.f;
#pragma unroll
        for (int off = 4; off; off >>= 1)
            ss += __shfl_xor_sync(0xffffffffu, ss, off);
        if (t == 0) red[0] = ss;
    }
    __syncthreads();
    float inv = 1.f / red[0];

    float p0 = e0 * inv, p1 = e1 * inv;
    arow[t] = p0; arow[t + 256] = p1;
    size_t base = (size_t)row * TSEQ;
    __nv_bfloat16 h0 = __float2bfloat16(p0);
    __nv_bfloat16 h1 = __float2bfloat16(p1);
    g_p_hi[base + t] = h0;       g_p_hi[base + t + 256] = h1;
    g_p_lo[base + t]       = __float2bfloat16(p0 - __bfloat162float(h0));
    g_p_lo[base + t + 256] = __float2bfloat16(p1 - __bfloat162float(h1));
}

// ============================================================================
// V transpose: VT[z][e][k] = V[b, k, h, e]  (bf16 hi/lo out)
// ============================================================================
__global__ void __launch_bounds__(256) v_transpose()
{
    int z = blockIdx.z;
    int b = z >> 3, h = z & 7;
    int k0 = blockIdx.x * 32, e0 = blockIdx.y * 32;
    __shared__ float tile[32][33];
    int tx = threadIdx.x & 31, ty = threadIdx.x >> 5;   // 32 x 8

#pragma unroll
    for (int s = 0; s < 4; s++) {
        int k = k0 + ty + s * 8;
        tile[ty + s * 8][tx] =
            g_qkv[(size_t)(b * TSEQ + k) * (3 * DMODEL) + 2 * DMODEL + h * HD + e0 + tx];
    }
    __syncthreads();
#pragma unroll
    for (int s = 0; s < 4; s++) {
        int e = e0 + ty + s * 8;
        float v = tile[tx][ty + s * 8];
        size_t idx = (size_t)z * (HD * TSEQ) + (size_t)e * TSEQ + k0 + tx;
        __nv_bfloat16 hh = __float2bfloat16(v);
        g_vt_hi[idx] = hh;
        g_vt_lo[idx] = __float2bfloat16(v - __bfloat162float(hh));
    }
}

// ============================================================================
// PEER routing (unchanged from R8)
// ============================================================================
__global__ void __launch_bounds__(128) peer_route(const float* __restrict__ expert_w)
{
    int row   = blockIdx.x;
    int token = row >> 3;
    int head  = row & 7;
    int tid   = threadIdx.x;

    __shared__ float q[128];
    __shared__ float sh1[128], sh2[128];
    __shared__ float v1[16], v2[16];
    __shared__ int   i1[16], i2[16];
    __shared__ float cv[50];
    __shared__ int   ci[50];
    __shared__ int   sel[16];
    __shared__ float simv[16];
    __shared__ float rw[16];
    __shared__ float ews[16][128];

    q[tid] = g_q[(size_t)token * HK + head * 128 + tid];
    float s1v = g_s[(size_t)row * 256 + tid];
    float s2v = g_s[(size_t)row * 256 + 128 + tid];
    sh1[tid] = s1v; sh2[tid] = s2v;
    __syncthreads();

    int r1 = 0, r2 = 0;
#pragma unroll 8
    for (int j = 0; j < 128; j++) {
        float w1 = sh1[j]; r1 += (w1 > s1v) || (w1 == s1v && j < tid);
        float w2 = sh2[j]; r2 += (w2 > s2v) || (w2 == s2v && j < tid);
    }
    if (r1 < 16) { v1[r1] = s1v; i1[r1] = tid; }
    if (r2 < 16) { v2[r2] = s2v; i2[r2] = tid; }
    __syncthreads();

    if (tid < 50) {
        int a = CAND_A[tid], b = CAND_B[tid];
        cv[tid] = v1[a] + v2[b];
        ci[tid] = i1[a] * NSUB + i2[b];
    }
    __syncthreads();
    if (tid < 50) {
        float v = cv[tid];
        int r = 0;
#pragma unroll 10
        for (int j = 0; j < 50; j++) {
            float w = cv[j];
            r += (w > v) || (w == v && j < tid);
        }
        if (r < 16) sel[r] = ci[tid];
    }
    __syncthreads();

#pragma unroll
    for (int k = 0; k < 16; k++)
        ews[k][tid] = expert_w[(size_t)sel[k] * DKEY + tid];
    __syncthreads();

    int k8 = tid >> 3, l8 = tid & 7;
    float part = 0.f;
#pragma unroll
    for (int i = 0; i < 16; i++) {
        int d = l8 * 16 + i;
        part += q[d] * ews[k8][d];
    }
    part += __shfl_down_sync(0xffffffffu, part, 4);
    part += __shfl_down_sync(0xffffffffu, part, 2);
    part += __shfl_down_sync(0xffffffffu, part, 1);
    if (l8 == 0) simv[k8] = part;
    __syncthreads();

    if (tid == 0) {
        float m = -INFINITY;
#pragma unroll
        for (int k = 0; k < 16; k++) m = fmaxf(m, simv[k]);
        float e[16]; float s = 0.f;
#pragma unroll
        for (int k = 0; k < 16; k++) { e[k] = expf(simv[k] - m); s += e[k]; }
        float inv = 1.f / s;
#pragma unroll
        for (int k = 0; k < 16; k++) rw[k] = e[k] * inv;
    }
    __syncthreads();

    float o = 0.f;
#pragma unroll
    for (int k = 0; k < 16; k++) o += rw[k] * ews[k][tid];
    size_t idx = (size_t)token * 2048 + head * 128 + tid;
    __nv_bfloat16 h = __float2bfloat16(o);
    g_cat_hi[idx] = h;
    g_cat_lo[idx] = __float2bfloat16(o - __bfloat162float(h));
}

// mean over heads (reads probs in g_att)
__global__ void __launch_bounds__(256) attn_mean(float* __restrict__ out)
{
    int idx = blockIdx.x * 256 + threadIdx.x;
    int b   = idx / (TSEQ * TSEQ);
    int rem = idx - b * (TSEQ * TSEQ);
    float s = 0.f;
#pragma unroll
    for (int h = 0; h < 8; h++)
        s += g_att[((size_t)(b * 8 + h)) * (TSEQ * TSEQ) + rem];
    out[idx] = s * 0.125f;
}

// y = rmsnorm(x + g_sum) * rms_w
__global__ void __launch_bounds__(256) final_rms(
    const float* __restrict__ x, const float* __restrict__ rms_w,
    float* __restrict__ y)
{
    int token = blockIdx.x;
    int t = threadIdx.x;
    size_t base = (size_t)token * DMODEL;
    float v[4];
    float ss = 0.f;
#pragma unroll
    for (int u = 0; u < 4; u++) {
        int c = t + u * 256;
        float s = x[base + c] + g_sum[base + c];
        v[u] = s;
        ss += s * s;
    }
#pragma unroll
    for (int off = 16; off; off >>= 1)
        ss += __shfl_xor_sync(0xffffffffu, ss, off);
    __shared__ float red[8];
    __shared__ float stot;
    if ((t & 31) == 0) red[t >> 5] = ss;
    __syncthreads();
    if (t == 0) {
        float s = 0.f;
#pragma unroll
        for (int i = 0; i < 8; i++) s += red[i];
        stot = rsqrtf(s * (1.f / DMODEL) + 1e-6f);
    }
    __syncthreads();
    float inv = stot;
#pragma unroll
    for (int u = 0; u < 4; u++) {
        int c = t + u * 256;
        y[base + c] = v[u] * inv * rms_w[c];
    }
}

// ============================================================================
extern "C" void kernel_launch(void* const* d_in, const int* in_sizes, int n_in,
                              void* d_out, int out_size)
{
    const float* x         = (const float*)d_in[0];
    const float* wq        = (const float*)d_in[1];
    const float* bq        = (const float*)d_in[2];
    const float* bn_w      = (const float*)d_in[3];
    const float* bn_b      = (const float*)d_in[4];
    const float* bn_mean   = (const float*)d_in[5];
    const float* bn_var    = (const float*)d_in[6];
    const float* sub_keys  = (const float*)d_in[7];
    const float* expert_w  = (const float*)d_in[8];
    const float* wo        = (const float*)d_in[9];
    const float* bo        = (const float*)d_in[10];
    const float* in_proj_w = (const float*)d_in[11];
    const float* in_proj_b = (const float*)d_in[12];
    const float* attn_ow   = (const float*)d_in[13];
    const float* attn_ob   = (const float*)d_in[14];
    const float* rms_w     = (const float*)d_in[15];

    float* y      = (float*)d_out;
    float* attn_w = (float*)d_out + (size_t)NTOK * DMODEL;

    void *p_q, *p_qkv, *p_sum, *p_s, *p_att;
    cudaGetSymbolAddress(&p_q, g_q);
    cudaGetSymbolAddress(&p_qkv, g_qkv);
    cudaGetSymbolAddress(&p_sum, g_sum);
    cudaGetSymbolAddress(&p_s, g_s);
    cudaGetSymbolAddress(&p_att, g_att);

    void *xh, *xl, *w1h, *w1l, *w2h, *w2l, *ch, *cl, *qbh, *qbl, *bdh, *bdl;
    void *qah, *qal, *kah, *kal, *ph, *pl, *vth, *vtl;
    cudaGetSymbolAddress(&xh,  g_x_hi);  cudaGetSymbolAddress(&xl,  g_x_lo);
    cudaGetSymbolAddress(&w1h, g_w1_hi); cudaGetSymbolAddress(&w1l, g_w1_lo);
    cudaGetSymbolAddress(&w2h, g_w2_hi); cudaGetSymbolAddress(&w2l, g_w2_lo);
    cudaGetSymbolAddress(&ch,  g_cat_hi); cudaGetSymbolAddress(&cl, g_cat_lo);
    cudaGetSymbolAddress(&qbh, g_qbn_hi); cudaGetSymbolAddress(&qbl, g_qbn_lo);
    cudaGetSymbolAddress(&bdh, g_bd_hi); cudaGetSymbolAddress(&bdl, g_bd_lo);
    cudaGetSymbolAddress(&qah, g_qa_hi); cudaGetSymbolAddress(&qal, g_qa_lo);
    cudaGetSymbolAddress(&kah, g_ka_hi); cudaGetSymbolAddress(&kal, g_ka_lo);
    cudaGetSymbolAddress(&ph,  g_p_hi);  cudaGetSymbolAddress(&pl,  g_p_lo);
    cudaGetSymbolAddress(&vth, g_vt_hi); cudaGetSymbolAddress(&vtl, g_vt_lo);

    constexpr int SMEM4 = 2 * (2 * 128 * 80 + 2 * 128 * 80);  // 81920
    constexpr int SMEM2 = 2 * (2 * 64 * 80 + 2 * 128 * 80);   // 61440
    cudaFuncSetAttribute(gemm_mma<4>, cudaFuncAttributeMaxDynamicSharedMemorySize, SMEM4);
    cudaFuncSetAttribute(gemm_mma<2>, cudaFuncAttributeMaxDynamicSharedMemorySize, SMEM2);

    const float scale = 0.08838834764831845f;   // 1/sqrt(128)

    // [0] split
    split_all<<<(int)((X4 + W14 + W24 + BD4) / 256), 256>>>(
        x, wq, in_proj_w, wo, attn_ow, sub_keys);

    // [1] fused q+qkv GEMM (mode 0): emits q/qkv fp32 + qbn/qa/ka bf16 hi/lo
    gemm_mma<4><<<dim3(4096 / 128, NTOK / 128), 256, SMEM4>>>(
        (const __nv_bfloat16*)xh, (const __nv_bfloat16*)xl,
        (const __nv_bfloat16*)w1h, (const __nv_bfloat16*)w1l,
        DMODEL, DMODEL, 0, 0,
        bq, in_proj_b, bn_mean, bn_var, bn_w, bn_b,
        0, 1.f,
        (float*)p_q, HK, (float*)p_qkv, 3 * DMODEL, 1024, 0, DMODEL);

    // [2] sub-key scores (mode 2): q_bn(8192x128) @ blockdiag(256x128)^T
    gemm_mma<4><<<dim3(2, 64), 256, SMEM4>>>(
        (const __nv_bfloat16*)qbh, (const __nv_bfloat16*)qbl,
        (const __nv_bfloat16*)bdh, (const __nv_bfloat16*)bdl,
        128, 128, 0, 0,
        nullptr, nullptr, nullptr, nullptr, nullptr, nullptr,
        2, 1.f,
        (float*)p_s, 256, (float*)p_s, 256, 1 << 30, 0, 128);

    // [3] QK^T batched GEMM (mode 3) -> raw scores in g_att   <- ncu slot
    gemm_mma<4><<<dim3(4, 4, NZ), 256, SMEM4>>>(
        (const __nv_bfloat16*)qah, (const __nv_bfloat16*)qal,
        (const __nv_bfloat16*)kah, (const __nv_bfloat16*)kal,
        HD, HD, (size_t)TSEQ * HD, (size_t)TSEQ * HD,
        nullptr, nullptr, nullptr, nullptr, nullptr, nullptr,
        3, scale,
        (float*)p_att, TSEQ, (float*)p_att, TSEQ, 1 << 30,
        (size_t)TSEQ * TSEQ, HD);

    // [4] softmax -> probs fp32 + P bf16 hi/lo
    attn_softmax<<<NZ * TSEQ, 256>>>();

    // [5] V transpose
    v_transpose<<<dim3(TSEQ / 32, HD / 32, NZ), 256>>>();

    // [6] PEER routing
    peer_route<<<NTOK * NHEADS, 128>>>(expert_w);

    // [7] AV batched GEMM (mode 4) -> cat bf16 hi/lo
    gemm_mma<2><<<dim3(1, 8, NZ), 256, SMEM2>>>(
        (const __nv_bfloat16*)ph, (const __nv_bfloat16*)pl,
        (const __nv_bfloat16*)vth, (const __nv_bfloat16*)vtl,
        TSEQ, TSEQ, (size_t)TSEQ * TSEQ, (size_t)HD * TSEQ,
        nullptr, nullptr, nullptr, nullptr, nullptr, nullptr,
        4, 1.f,
        nullptr, 0, nullptr, 0, 1 << 30, 0, TSEQ);

    // [8] attn_weights = mean over heads
    attn_mean<<<(BATCH * TSEQ * TSEQ) / 256, 256>>>(attn_w);

    // [9] fused output projection (mode 1)
    gemm_mma<2><<<dim3(DMODEL / 128, NTOK / 64), 256, SMEM2>>>(
        (const __nv_bfloat16*)ch, (const __nv_bfloat16*)cl,
        (const __nv_bfloat16*)w2h, (const __nv_bfloat16*)w2l,
        2048, 2048, 0, 0,
        bo, attn_ob, nullptr, nullptr, nullptr, nullptr,
        1, 1.f,
        (float*)p_sum, DMODEL, (float*)p_sum, DMODEL, 1 << 30, 0, 2048);

    // [10] residual + rmsnorm
    final_rms<<<NTOK, 256>>>(x, rms_w, y);

    (void)in_sizes; (void)n_in; (void)out_size;
}